// round 8
// baseline (speedup 1.0000x reference)
#include <cuda_runtime.h>
#include <cuda_bf16.h>
#include <cstdint>

// ---------------------------------------------------------------------------
// Problem constants
// ---------------------------------------------------------------------------
#define NMAX 100000
#define EMAX 1600000
#define FIN  512
#define HID  64
#define NH1  8
#define C2   16
#define NEG_SLOPE 0.2f
#define EPSV 1e-16f
#define NCHUNK 32            // K chunks of 16

// ---------------------------------------------------------------------------
// Device scratch
// ---------------------------------------------------------------------------
__device__ float g_h1[(size_t)NMAX * HID];
__device__ float g_helu[(size_t)NMAX * HID];
__device__ float g_y2[(size_t)NMAX * C2];
__device__ float g_as1[(size_t)NMAX * NH1];
__device__ float g_ad1[(size_t)NMAX * NH1];
__device__ float g_as2[NMAX];
__device__ float g_ad2[NMAX];
__device__ int   g_rowptr[NMAX + 1];
__device__ int   g_head[NMAX];
__device__ int   g_cnt[NMAX];
__device__ int   g_col[EMAX];
__device__ int   g_bsum[128];
__device__ int   g_boff[128];
__device__ int   g_is64;
// W1 pre-converted to mma-fragment-major bf16 hi/lo
__device__ uint32_t g_wf[NCHUNK * 1024];

__device__ __forceinline__ float lrelu(float v) { return v > 0.f ? v : NEG_SLOPE * v; }

__device__ __forceinline__ uint32_t pack_bf16x2(float a, float b) {
    __nv_bfloat162 h = __floats2bfloat162_rn(a, b);
    return *(uint32_t*)&h;
}
__device__ __forceinline__ void split_pair(float a, float b, uint32_t& hi, uint32_t& lo) {
    __nv_bfloat16 ha = __float2bfloat16_rn(a), hb = __float2bfloat16_rn(b);
    float ra = a - __bfloat162float(ha);
    float rb = b - __bfloat162float(hb);
    __nv_bfloat162 hh; hh.x = ha; hh.y = hb;
    hi = *(uint32_t*)&hh;
    lo = pack_bf16x2(ra, rb);
}

__device__ __forceinline__ void mma_bf16(float* c, uint32_t a0, uint32_t a1,
                                         uint32_t a2, uint32_t a3,
                                         uint32_t b0, uint32_t b1) {
    asm("mma.sync.aligned.m16n8k16.row.col.f32.bf16.bf16.f32 "
        "{%0,%1,%2,%3}, {%4,%5,%6,%7}, {%8,%9}, {%0,%1,%2,%3};"
        : "+f"(c[0]), "+f"(c[1]), "+f"(c[2]), "+f"(c[3])
        : "r"(a0), "r"(a1), "r"(a2), "r"(a3), "r"(b0), "r"(b1));
}

// ---------------------------------------------------------------------------
// edge dtype detection
// ---------------------------------------------------------------------------
__global__ void detect_kernel(const long long* p, int N, int E) {
    if (threadIdx.x == 0 && blockIdx.x == 0) {
        int n = E < 64 ? E : 64;
        int ok = 1;
        for (int i = 0; i < n; i++) {
            long long v = p[i];
            if (v < 0 || v >= (long long)N) { ok = 0; break; }
        }
        g_is64 = ok;
    }
}

__global__ void zero_cnt_kernel(int N) {
    int i = blockIdx.x * blockDim.x + threadIdx.x;
    if (i < N) g_cnt[i] = 0;
}

__global__ void count_kernel(const void* ei, int E, int N) {
    int e = blockIdx.x * blockDim.x + threadIdx.x;
    if (e >= E) return;
    int d = g_is64 ? (int)((const long long*)ei)[(size_t)E + e]
                   : ((const int*)ei)[(size_t)E + e];
    atomicAdd(&g_cnt[d], 1);
}

// ---------------------------------------------------------------------------
// multi-block exclusive scan
// ---------------------------------------------------------------------------
__global__ __launch_bounds__(1024) void scan1_kernel(int N) {
    __shared__ int ws[32];
    int tid = threadIdx.x, lane = tid & 31, w = tid >> 5;
    int i = blockIdx.x * 1024 + tid;
    int v = (i < N) ? g_cnt[i] : 0;
    int x = v;
    #pragma unroll
    for (int d = 1; d < 32; d <<= 1) {
        int t = __shfl_up_sync(0xffffffffu, x, d);
        if (lane >= d) x += t;
    }
    if (lane == 31) ws[w] = x;
    __syncthreads();
    if (tid < 32) {
        int s = ws[tid];
        #pragma unroll
        for (int d = 1; d < 32; d <<= 1) {
            int t = __shfl_up_sync(0xffffffffu, s, d);
            if (tid >= d) s += t;
        }
        ws[tid] = s;
    }
    __syncthreads();
    int incl = x + (w > 0 ? ws[w - 1] : 0);
    if (i < N) g_rowptr[i] = incl - v;
    if (tid == 1023) g_bsum[blockIdx.x] = incl;
}

__global__ void scan2_kernel(int NB, int N) {
    __shared__ int ws[4];
    int tid = threadIdx.x, lane = tid & 31, w = tid >> 5;
    int v = (tid < NB) ? g_bsum[tid] : 0;
    int x = v;
    #pragma unroll
    for (int d = 1; d < 32; d <<= 1) {
        int t = __shfl_up_sync(0xffffffffu, x, d);
        if (lane >= d) x += t;
    }
    if (lane == 31) ws[w] = x;
    __syncthreads();
    if (tid < 4) {
        int s = ws[tid];
        for (int d = 1; d < 4; d <<= 1) {
            int t = __shfl_up_sync(0xfu, s, d);
            if (tid >= d) s += t;
        }
        ws[tid] = s;
    }
    __syncthreads();
    int incl = x + (w > 0 ? ws[w - 1] : 0);
    if (tid < NB) g_boff[tid] = incl - v;
    if (tid == NB - 1) g_rowptr[N] = incl;
}

__global__ __launch_bounds__(1024) void scan3_kernel(int N) {
    int i = blockIdx.x * 1024 + threadIdx.x;
    if (i < N) {
        int r = g_rowptr[i] + g_boff[blockIdx.x];
        g_rowptr[i] = r;
        g_head[i] = r;
    }
}

__global__ void scatter_kernel(const void* ei, int E) {
    int e = blockIdx.x * blockDim.x + threadIdx.x;
    if (e >= E) return;
    int s, d;
    if (g_is64) {
        s = (int)((const long long*)ei)[e];
        d = (int)((const long long*)ei)[(size_t)E + e];
    } else {
        s = ((const int*)ei)[e];
        d = ((const int*)ei)[(size_t)E + e];
    }
    int p = atomicAdd(&g_head[d], 1);
    g_col[p] = s;
}

// ---------------------------------------------------------------------------
// W1 -> fragment-major bf16 hi/lo conversion (runs once, 16384 threads)
// ---------------------------------------------------------------------------
__global__ void convW_kernel(const float* __restrict__ W) {
    int t = blockIdx.x * 256 + threadIdx.x;
    if (t >= NCHUNK * 2 * 8 * 32) return;
    int lane = t & 31;
    int nt = (t >> 5) & 7;
    int r  = (t >> 8) & 1;
    int c  = t >> 9;
    int grp = lane >> 2, q = lane & 3;
    int k = c * 16 + r * 8 + q * 2;
    int n = nt * 8 + grp;
    float w0 = W[(size_t)k * HID + n];
    float w1 = W[(size_t)(k + 1) * HID + n];
    uint32_t hi, lo;
    split_pair(w0, w1, hi, lo);
    g_wf[c * 1024 +       (r * 8 + nt) * 32 + lane] = hi;
    g_wf[c * 1024 + 512 + (r * 8 + nt) * 32 + lane] = lo;
}

// ---------------------------------------------------------------------------
// GEMM1: h1[N,64] = x[N,512] @ W1 via mma.sync bf16 hi/lo (3 terms).
// 256 threads = 8 warps x 16 rows. Fused attn1 epilogue (head == n-tile).
// ---------------------------------------------------------------------------
#define APAD 10
__global__ __launch_bounds__(256) void gemm1_mma_kernel(const float* __restrict__ x,
                                                        const float* __restrict__ att_s,
                                                        const float* __restrict__ att_d,
                                                        int Nn) {
    __shared__ uint32_t sAh[128 * APAD];
    __shared__ uint32_t sAl[128 * APAD];
    __shared__ uint32_t sW[1024];

    int tid = threadIdx.x;
    int w = tid >> 5, lane = tid & 31;
    int grp = lane >> 2, q = lane & 3;
    int row0 = blockIdx.x * 128;

    int arow = tid >> 1;
    int acol8 = (tid & 1) * 8;
    int grow_a = row0 + arow;
    const float* abase = x + (size_t)(grow_a < Nn ? grow_a : (Nn - 1)) * FIN + acol8;

    float acc[8][4];
    #pragma unroll
    for (int nt = 0; nt < 8; nt++)
        #pragma unroll
        for (int i = 0; i < 4; i++) acc[nt][i] = 0.f;

    float4 pa0 = *(const float4*)(abase + 0);
    float4 pa1 = *(const float4*)(abase + 4);
    uint4  pw  = *(const uint4*)&g_wf[0 * 1024 + tid * 4];

    for (int c = 0; c < NCHUNK; c++) {
        __syncthreads();
        {
            uint32_t h0, l0, h1, l1, h2, l2, h3, l3;
            split_pair(pa0.x, pa0.y, h0, l0);
            split_pair(pa0.z, pa0.w, h1, l1);
            split_pair(pa1.x, pa1.y, h2, l2);
            split_pair(pa1.z, pa1.w, h3, l3);
            int off = arow * APAD + (tid & 1) * 4;
            *(uint2*)&sAh[off]     = make_uint2(h0, h1);
            *(uint2*)&sAh[off + 2] = make_uint2(h2, h3);
            *(uint2*)&sAl[off]     = make_uint2(l0, l1);
            *(uint2*)&sAl[off + 2] = make_uint2(l2, l3);
            *(uint4*)&sW[tid * 4] = pw;
        }
        if (c + 1 < NCHUNK) {
            pa0 = *(const float4*)(abase + (c + 1) * 16 + 0);
            pa1 = *(const float4*)(abase + (c + 1) * 16 + 4);
            pw  = *(const uint4*)&g_wf[(c + 1) * 1024 + tid * 4];
        }
        __syncthreads();
        int ab = w * 16;
        uint32_t ah0 = sAh[(ab + grp) * APAD + q];
        uint32_t ah1 = sAh[(ab + 8 + grp) * APAD + q];
        uint32_t ah2 = sAh[(ab + grp) * APAD + 4 + q];
        uint32_t ah3 = sAh[(ab + 8 + grp) * APAD + 4 + q];
        uint32_t al0 = sAl[(ab + grp) * APAD + q];
        uint32_t al1 = sAl[(ab + 8 + grp) * APAD + q];
        uint32_t al2 = sAl[(ab + grp) * APAD + 4 + q];
        uint32_t al3 = sAl[(ab + 8 + grp) * APAD + 4 + q];
        #pragma unroll
        for (int nt = 0; nt < 8; nt++) {
            uint32_t bh0 = sW[(0 * 8 + nt) * 32 + lane];
            uint32_t bh1 = sW[(1 * 8 + nt) * 32 + lane];
            uint32_t bl0 = sW[512 + (0 * 8 + nt) * 32 + lane];
            uint32_t bl1 = sW[512 + (1 * 8 + nt) * 32 + lane];
            mma_bf16(acc[nt], ah0, ah1, ah2, ah3, bh0, bh1);
            mma_bf16(acc[nt], ah0, ah1, ah2, ah3, bl0, bl1);
            mma_bf16(acc[nt], al0, al1, al2, al3, bh0, bh1);
        }
    }

    // epilogue: store h1 + fused per-head attention dots (head == nt)
    int r0 = row0 + w * 16 + grp;
    int r1 = r0 + 8;
    #pragma unroll
    for (int nt = 0; nt < 8; nt++) {
        int col = nt * 8 + q * 2;
        if (r0 < Nn) *(float2*)&g_h1[(size_t)r0 * HID + col] = make_float2(acc[nt][0], acc[nt][1]);
        if (r1 < Nn) *(float2*)&g_h1[(size_t)r1 * HID + col] = make_float2(acc[nt][2], acc[nt][3]);
        float2 a_s = *(const float2*)&att_s[col];
        float2 a_d = *(const float2*)&att_d[col];
        float p0s = acc[nt][0] * a_s.x + acc[nt][1] * a_s.y;
        float p0d = acc[nt][0] * a_d.x + acc[nt][1] * a_d.y;
        float p1s = acc[nt][2] * a_s.x + acc[nt][3] * a_s.y;
        float p1d = acc[nt][2] * a_d.x + acc[nt][3] * a_d.y;
        p0s += __shfl_xor_sync(0xffffffffu, p0s, 1);
        p0s += __shfl_xor_sync(0xffffffffu, p0s, 2);
        p0d += __shfl_xor_sync(0xffffffffu, p0d, 1);
        p0d += __shfl_xor_sync(0xffffffffu, p0d, 2);
        p1s += __shfl_xor_sync(0xffffffffu, p1s, 1);
        p1s += __shfl_xor_sync(0xffffffffu, p1s, 2);
        p1d += __shfl_xor_sync(0xffffffffu, p1d, 1);
        p1d += __shfl_xor_sync(0xffffffffu, p1d, 2);
        if (q == 0) {
            if (r0 < Nn) { g_as1[(size_t)r0 * NH1 + nt] = p0s; g_ad1[(size_t)r0 * NH1 + nt] = p0d; }
            if (r1 < Nn) { g_as1[(size_t)r1 * NH1 + nt] = p1s; g_ad1[(size_t)r1 * NH1 + nt] = p1d; }
        }
    }
}

// ---------------------------------------------------------------------------
// layer-1 fused softmax+aggregate, single pass. One warp per node.
// ---------------------------------------------------------------------------
__global__ __launch_bounds__(256) void agg1_kernel(const float* __restrict__ bias1, int N) {
    int node = (blockIdx.x * blockDim.x + threadIdx.x) >> 5;
    int lane = threadIdx.x & 31;
    if (node >= N) return;
    int start = g_rowptr[node];
    int deg   = g_rowptr[node + 1] - start;
    int hl = lane & 7;
    int hh = lane >> 2;

    float adv   = g_ad1[(size_t)node * NH1 + hl];
    float selfe = __expf(lrelu(g_as1[(size_t)node * NH1 + hl] + adv));
    float2 hv = *(const float2*)&g_h1[(size_t)node * HID + 2 * lane];

    float ax = 0.f, ay = 0.f;
    float s = 0.f;
    for (int base = 0; base < deg; base += 4) {
        int idx = base + (lane >> 3);
        int j = 0; float wt = 0.f;
        if (idx < deg) {
            j = g_col[start + idx];
            wt = __expf(lrelu(g_as1[(size_t)j * NH1 + hl] + adv));
        }
        s += wt;
        int nb = min(4, deg - base);
        #pragma unroll
        for (int e = 0; e < 4; e++) {
            if (e >= nb) break;
            float we = __shfl_sync(0xffffffffu, wt, e * 8 + hh);
            int je   = __shfl_sync(0xffffffffu, j, e * 8);
            float2 v = *(const float2*)&g_h1[(size_t)je * HID + 2 * lane];
            ax = fmaf(we, v.x, ax);
            ay = fmaf(we, v.y, ay);
        }
    }
    s += __shfl_xor_sync(0xffffffffu, s, 8);
    s += __shfl_xor_sync(0xffffffffu, s, 16);
    s += selfe;
    float inv = 1.f / (s + EPSV);
    float invB   = __shfl_sync(0xffffffffu, inv, hh);
    float selfeB = __shfl_sync(0xffffffffu, selfe, hh);
    ax = (ax + selfeB * hv.x) * invB;
    ay = (ay + selfeB * hv.y) * invB;
    float2 bb = *(const float2*)&bias1[2 * lane];
    ax += bb.x; ay += bb.y;
    ax = ax > 0.f ? ax : (__expf(ax) - 1.f);
    ay = ay > 0.f ? ay : (__expf(ay) - 1.f);
    *(float2*)&g_helu[(size_t)node * HID + 2 * lane] = make_float2(ax, ay);
}

// ---------------------------------------------------------------------------
// layer-2 GEMM (thread per node) + attention scalars
// ---------------------------------------------------------------------------
__global__ __launch_bounds__(256) void gemm2_kernel(const float* __restrict__ W2,
                                                    const float* __restrict__ att_s,
                                                    const float* __restrict__ att_d,
                                                    int N) {
    __shared__ float sW[HID * C2];
    __shared__ float sas[C2], sad[C2];
    int tid = threadIdx.x;
    for (int i = tid; i < HID * C2; i += blockDim.x) sW[i] = W2[i];
    if (tid < C2) { sas[tid] = att_s[tid]; sad[tid] = att_d[tid]; }
    __syncthreads();
    int n = blockIdx.x * blockDim.x + tid;
    if (n >= N) return;
    float acc[C2];
    #pragma unroll
    for (int c = 0; c < C2; c++) acc[c] = 0.f;
    const float* hr = &g_helu[(size_t)n * HID];
    #pragma unroll
    for (int k = 0; k < HID; k += 4) {
        float4 h4 = *(const float4*)&hr[k];
        #pragma unroll
        for (int c = 0; c < C2; c++) {
            acc[c] = fmaf(h4.x, sW[(k + 0) * C2 + c], acc[c]);
            acc[c] = fmaf(h4.y, sW[(k + 1) * C2 + c], acc[c]);
            acc[c] = fmaf(h4.z, sW[(k + 2) * C2 + c], acc[c]);
            acc[c] = fmaf(h4.w, sW[(k + 3) * C2 + c], acc[c]);
        }
    }
    #pragma unroll
    for (int c = 0; c < C2; c += 4)
        *(float4*)&g_y2[(size_t)n * C2 + c] = make_float4(acc[c], acc[c+1], acc[c+2], acc[c+3]);
    float ps = 0.f, pd = 0.f;
    #pragma unroll
    for (int c = 0; c < C2; c++) { ps = fmaf(acc[c], sas[c], ps); pd = fmaf(acc[c], sad[c], pd); }
    g_as2[n] = ps;
    g_ad2[n] = pd;
}

// ---------------------------------------------------------------------------
// layer-2 fused softmax+aggregate, single pass + bias + final softmax
// ---------------------------------------------------------------------------
__global__ __launch_bounds__(256) void agg2_kernel(const float* __restrict__ bias2,
                                                   float* __restrict__ out, int N) {
    int node = (blockIdx.x * blockDim.x + threadIdx.x) >> 5;
    int lane = threadIdx.x & 31;
    if (node >= N) return;
    int start = g_rowptr[node];
    int deg   = g_rowptr[node + 1] - start;

    float ad    = g_ad2[node];
    float selfe = __expf(lrelu(g_as2[node] + ad));
    int c = lane & 15, half = lane >> 4;

    float acc = 0.f;
    float s = 0.f;
    for (int base = 0; base < deg; base += 32) {
        int idx = base + lane;
        int j = 0; float wt = 0.f;
        if (idx < deg) {
            j = g_col[start + idx];
            wt = __expf(lrelu(g_as2[j] + ad));
        }
        s += wt;
        int nb = min(32, deg - base);
        for (int p = 0; p < nb; p += 2) {
            int e = p + half;
            float we = __shfl_sync(0xffffffffu, wt, e & 31);
            int je   = __shfl_sync(0xffffffffu, j, e & 31);
            if (e < nb) acc = fmaf(we, g_y2[(size_t)je * C2 + c], acc);
        }
    }
    #pragma unroll
    for (int d = 16; d >= 1; d >>= 1)
        s += __shfl_xor_sync(0xffffffffu, s, d);
    s += selfe;
    float inv = 1.f / (s + EPSV);

    acc += __shfl_xor_sync(0xffffffffu, acc, 16);
    acc = (acc + selfe * g_y2[(size_t)node * C2 + c]) * inv;
    acc += bias2[c];

    float mx = acc;
    #pragma unroll
    for (int d = 8; d >= 1; d >>= 1)
        mx = fmaxf(mx, __shfl_xor_sync(0xffffffffu, mx, d));
    float p = __expf(acc - mx);
    float ss = p;
    #pragma unroll
    for (int d = 8; d >= 1; d >>= 1)
        ss += __shfl_xor_sync(0xffffffffu, ss, d);
    float soft = p / ss;

    if (lane < 16) {
        out[(size_t)node * C2 + c] = soft;
        out[(size_t)N * C2 + (size_t)node * C2 + c] = acc;
    }
}

// ---------------------------------------------------------------------------
// launch: CSR build (default stream) runs CONCURRENT with convW+gemm1 (s2).
// Fork/join via events — graph-capture legal, handles created once lazily.
// ---------------------------------------------------------------------------
extern "C" void kernel_launch(void* const* d_in, const int* in_sizes, int n_in,
                              void* d_out, int out_size) {
    const float* x   = (const float*)d_in[0];
    const void*  ei  = d_in[1];
    const float* W1  = (const float*)d_in[2];
    const float* as1 = (const float*)d_in[3];
    const float* ad1 = (const float*)d_in[4];
    const float* b1  = (const float*)d_in[5];
    const float* W2  = (const float*)d_in[6];
    const float* as2 = (const float*)d_in[7];
    const float* ad2 = (const float*)d_in[8];
    const float* b2  = (const float*)d_in[9];
    float* out = (float*)d_out;

    int E = in_sizes[1] / 2;
    int N = in_sizes[0] / FIN;
    int NB = (N + 1023) / 1024;

    static cudaStream_t s2 = nullptr;
    static cudaEvent_t evFork = nullptr, evJoin = nullptr;
    if (s2 == nullptr) {
        cudaStreamCreateWithFlags(&s2, cudaStreamNonBlocking);
        cudaEventCreateWithFlags(&evFork, cudaEventDisableTiming);
        cudaEventCreateWithFlags(&evJoin, cudaEventDisableTiming);
    }

    // fork: side stream runs the GEMM1 chain (independent of edge data)
    cudaEventRecord(evFork, 0);
    cudaStreamWaitEvent(s2, evFork, 0);
    convW_kernel<<<64, 256, 0, s2>>>(W1);
    gemm1_mma_kernel<<<(N + 127) / 128, 256, 0, s2>>>(x, as1, ad1, N);
    cudaEventRecord(evJoin, s2);

    // default stream: CSR build chain
    detect_kernel<<<1, 32>>>((const long long*)ei, N, E);
    zero_cnt_kernel<<<(N + 255) / 256, 256>>>(N);
    count_kernel<<<(E + 255) / 256, 256>>>(ei, E, N);
    scan1_kernel<<<NB, 1024>>>(N);
    scan2_kernel<<<1, 128>>>(NB, N);
    scan3_kernel<<<NB, 1024>>>(N);
    scatter_kernel<<<(E + 255) / 256, 256>>>(ei, E);

    // join: agg1 needs both CSR and h1/as1/ad1
    cudaStreamWaitEvent(0, evJoin, 0);
    agg1_kernel<<<(N + 7) / 8, 256>>>(b1, N);
    gemm2_kernel<<<(N + 255) / 256, 256>>>(W2, as2, ad2, N);
    agg2_kernel<<<(N + 7) / 8, 256>>>(b2, out, N);
}

// round 10
// speedup vs baseline: 1.0086x; 1.0086x over previous
#include <cuda_runtime.h>
#include <cuda_bf16.h>
#include <cstdint>

// ---------------------------------------------------------------------------
// Problem constants
// ---------------------------------------------------------------------------
#define NMAX 100000
#define EMAX 1600000
#define FIN  512
#define HID  64
#define NH1  8
#define C2   16
#define NEG_SLOPE 0.2f
#define EPSV 1e-16f
#define NCHUNK 32            // K chunks of 16

// ---------------------------------------------------------------------------
// Device scratch
// ---------------------------------------------------------------------------
__device__ float g_h1[(size_t)NMAX * HID];
__device__ float g_helu[(size_t)NMAX * HID];
__device__ float g_y2[(size_t)NMAX * C2];
__device__ float g_as1[(size_t)NMAX * NH1];
__device__ float g_ad1[(size_t)NMAX * NH1];
__device__ float g_as2[NMAX];
__device__ float g_ad2[NMAX];
__device__ int   g_rowptr[NMAX + 1];
__device__ int   g_head[NMAX];
__device__ int   g_cnt[NMAX];          // zero-init at load; scan1 re-zeroes
__device__ int   g_col[EMAX];
__device__ int   g_bsum[128];
__device__ int   g_boff[128];
__device__ int   g_is64;
// W1 pre-converted to mma-fragment-major bf16 hi/lo
__device__ uint32_t g_wf[NCHUNK * 1024];

__device__ __forceinline__ float lrelu(float v) { return v > 0.f ? v : NEG_SLOPE * v; }

__device__ __forceinline__ uint32_t pack_bf16x2(float a, float b) {
    __nv_bfloat162 h = __floats2bfloat162_rn(a, b);
    return *(uint32_t*)&h;
}
__device__ __forceinline__ void split_pair(float a, float b, uint32_t& hi, uint32_t& lo) {
    __nv_bfloat16 ha = __float2bfloat16_rn(a), hb = __float2bfloat16_rn(b);
    float ra = a - __bfloat162float(ha);
    float rb = b - __bfloat162float(hb);
    __nv_bfloat162 hh; hh.x = ha; hh.y = hb;
    hi = *(uint32_t*)&hh;
    lo = pack_bf16x2(ra, rb);
}

__device__ __forceinline__ void mma_bf16(float* c, uint32_t a0, uint32_t a1,
                                         uint32_t a2, uint32_t a3,
                                         uint32_t b0, uint32_t b1) {
    asm("mma.sync.aligned.m16n8k16.row.col.f32.bf16.bf16.f32 "
        "{%0,%1,%2,%3}, {%4,%5,%6,%7}, {%8,%9}, {%0,%1,%2,%3};"
        : "+f"(c[0]), "+f"(c[1]), "+f"(c[2]), "+f"(c[3])
        : "r"(a0), "r"(a1), "r"(a2), "r"(a3), "r"(b0), "r"(b1));
}

// ---------------------------------------------------------------------------
// edge dtype detection
// ---------------------------------------------------------------------------
__global__ void detect_kernel(const long long* p, int N, int E) {
    if (threadIdx.x == 0 && blockIdx.x == 0) {
        int n = E < 64 ? E : 64;
        int ok = 1;
        for (int i = 0; i < n; i++) {
            long long v = p[i];
            if (v < 0 || v >= (long long)N) { ok = 0; break; }
        }
        g_is64 = ok;
    }
}

// count: 2 edges per thread, vectorized loads of the dst half
__global__ void count_kernel(const void* ei, int E, int N) {
    int t = blockIdx.x * blockDim.x + threadIdx.x;
    int e = t * 2;
    if (e >= E) return;
    int d0, d1;
    if (g_is64) {
        longlong2 v = *(const longlong2*)((const long long*)ei + (size_t)E + e);
        d0 = (int)v.x; d1 = (int)v.y;
    } else {
        int2 v = *(const int2*)((const int*)ei + (size_t)E + e);
        d0 = v.x; d1 = v.y;
    }
    atomicAdd(&g_cnt[d0], 1);
    if (e + 1 < E) atomicAdd(&g_cnt[d1], 1);
}

// ---------------------------------------------------------------------------
// multi-block exclusive scan (scan1 also re-zeroes g_cnt for the next replay)
// ---------------------------------------------------------------------------
__global__ __launch_bounds__(1024) void scan1_kernel(int N) {
    __shared__ int ws[32];
    int tid = threadIdx.x, lane = tid & 31, w = tid >> 5;
    int i = blockIdx.x * 1024 + tid;
    int v = (i < N) ? g_cnt[i] : 0;
    if (i < N) g_cnt[i] = 0;           // reset for next graph replay
    int x = v;
    #pragma unroll
    for (int d = 1; d < 32; d <<= 1) {
        int t = __shfl_up_sync(0xffffffffu, x, d);
        if (lane >= d) x += t;
    }
    if (lane == 31) ws[w] = x;
    __syncthreads();
    if (tid < 32) {
        int s = ws[tid];
        #pragma unroll
        for (int d = 1; d < 32; d <<= 1) {
            int t = __shfl_up_sync(0xffffffffu, s, d);
            if (tid >= d) s += t;
        }
        ws[tid] = s;
    }
    __syncthreads();
    int incl = x + (w > 0 ? ws[w - 1] : 0);
    if (i < N) g_rowptr[i] = incl - v;
    if (tid == 1023) g_bsum[blockIdx.x] = incl;
}

__global__ void scan2_kernel(int NB, int N) {
    __shared__ int ws[4];
    int tid = threadIdx.x, lane = tid & 31, w = tid >> 5;
    int v = (tid < NB) ? g_bsum[tid] : 0;
    int x = v;
    #pragma unroll
    for (int d = 1; d < 32; d <<= 1) {
        int t = __shfl_up_sync(0xffffffffu, x, d);
        if (lane >= d) x += t;
    }
    if (lane == 31) ws[w] = x;
    __syncthreads();
    if (tid < 4) {
        int s = ws[tid];
        for (int d = 1; d < 4; d <<= 1) {
            int t = __shfl_up_sync(0xfu, s, d);
            if (tid >= d) s += t;
        }
        ws[tid] = s;
    }
    __syncthreads();
    int incl = x + (w > 0 ? ws[w - 1] : 0);
    if (tid < NB) g_boff[tid] = incl - v;
    if (tid == NB - 1) g_rowptr[N] = incl;
}

__global__ __launch_bounds__(1024) void scan3_kernel(int N) {
    int i = blockIdx.x * 1024 + threadIdx.x;
    if (i < N) {
        int r = g_rowptr[i] + g_boff[blockIdx.x];
        g_rowptr[i] = r;
        g_head[i] = r;
    }
}

// scatter: 2 edges per thread, vectorized loads
__global__ void scatter_kernel(const void* ei, int E) {
    int t = blockIdx.x * blockDim.x + threadIdx.x;
    int e = t * 2;
    if (e >= E) return;
    int s0, s1, d0, d1;
    if (g_is64) {
        longlong2 sv = *(const longlong2*)((const long long*)ei + e);
        longlong2 dv = *(const longlong2*)((const long long*)ei + (size_t)E + e);
        s0 = (int)sv.x; s1 = (int)sv.y; d0 = (int)dv.x; d1 = (int)dv.y;
    } else {
        int2 sv = *(const int2*)((const int*)ei + e);
        int2 dv = *(const int2*)((const int*)ei + (size_t)E + e);
        s0 = sv.x; s1 = sv.y; d0 = dv.x; d1 = dv.y;
    }
    int p0 = atomicAdd(&g_head[d0], 1);
    g_col[p0] = s0;
    if (e + 1 < E) {
        int p1 = atomicAdd(&g_head[d1], 1);
        g_col[p1] = s1;
    }
}

// ---------------------------------------------------------------------------
// W1 -> fragment-major bf16 hi/lo conversion
// ---------------------------------------------------------------------------
__global__ void convW_kernel(const float* __restrict__ W) {
    int t = blockIdx.x * 256 + threadIdx.x;
    if (t >= NCHUNK * 2 * 8 * 32) return;
    int lane = t & 31;
    int nt = (t >> 5) & 7;
    int r  = (t >> 8) & 1;
    int c  = t >> 9;
    int grp = lane >> 2, q = lane & 3;
    int k = c * 16 + r * 8 + q * 2;
    int n = nt * 8 + grp;
    float w0 = W[(size_t)k * HID + n];
    float w1 = W[(size_t)(k + 1) * HID + n];
    uint32_t hi, lo;
    split_pair(w0, w1, hi, lo);
    g_wf[c * 1024 +       (r * 8 + nt) * 32 + lane] = hi;
    g_wf[c * 1024 + 512 + (r * 8 + nt) * 32 + lane] = lo;
}

// ---------------------------------------------------------------------------
// GEMM1 via mma.sync bf16 hi/lo (3 terms) + fused attn1 epilogue
// ---------------------------------------------------------------------------
#define APAD 10
__global__ __launch_bounds__(256) void gemm1_mma_kernel(const float* __restrict__ x,
                                                        const float* __restrict__ att_s,
                                                        const float* __restrict__ att_d,
                                                        int Nn) {
    __shared__ uint32_t sAh[128 * APAD];
    __shared__ uint32_t sAl[128 * APAD];
    __shared__ uint32_t sW[1024];

    int tid = threadIdx.x;
    int w = tid >> 5, lane = tid & 31;
    int grp = lane >> 2, q = lane & 3;
    int row0 = blockIdx.x * 128;

    int arow = tid >> 1;
    int acol8 = (tid & 1) * 8;
    int grow_a = row0 + arow;
    const float* abase = x + (size_t)(grow_a < Nn ? grow_a : (Nn - 1)) * FIN + acol8;

    float acc[8][4];
    #pragma unroll
    for (int nt = 0; nt < 8; nt++)
        #pragma unroll
        for (int i = 0; i < 4; i++) acc[nt][i] = 0.f;

    float4 pa0 = *(const float4*)(abase + 0);
    float4 pa1 = *(const float4*)(abase + 4);
    uint4  pw  = *(const uint4*)&g_wf[0 * 1024 + tid * 4];

    for (int c = 0; c < NCHUNK; c++) {
        __syncthreads();
        {
            uint32_t h0, l0, h1, l1, h2, l2, h3, l3;
            split_pair(pa0.x, pa0.y, h0, l0);
            split_pair(pa0.z, pa0.w, h1, l1);
            split_pair(pa1.x, pa1.y, h2, l2);
            split_pair(pa1.z, pa1.w, h3, l3);
            int off = arow * APAD + (tid & 1) * 4;
            *(uint2*)&sAh[off]     = make_uint2(h0, h1);
            *(uint2*)&sAh[off + 2] = make_uint2(h2, h3);
            *(uint2*)&sAl[off]     = make_uint2(l0, l1);
            *(uint2*)&sAl[off + 2] = make_uint2(l2, l3);
            *(uint4*)&sW[tid * 4] = pw;
        }
        if (c + 1 < NCHUNK) {
            pa0 = *(const float4*)(abase + (c + 1) * 16 + 0);
            pa1 = *(const float4*)(abase + (c + 1) * 16 + 4);
            pw  = *(const uint4*)&g_wf[(c + 1) * 1024 + tid * 4];
        }
        __syncthreads();
        int ab = w * 16;
        uint32_t ah0 = sAh[(ab + grp) * APAD + q];
        uint32_t ah1 = sAh[(ab + 8 + grp) * APAD + q];
        uint32_t ah2 = sAh[(ab + grp) * APAD + 4 + q];
        uint32_t ah3 = sAh[(ab + 8 + grp) * APAD + 4 + q];
        uint32_t al0 = sAl[(ab + grp) * APAD + q];
        uint32_t al1 = sAl[(ab + 8 + grp) * APAD + q];
        uint32_t al2 = sAl[(ab + grp) * APAD + 4 + q];
        uint32_t al3 = sAl[(ab + 8 + grp) * APAD + 4 + q];
        #pragma unroll
        for (int nt = 0; nt < 8; nt++) {
            uint32_t bh0 = sW[(0 * 8 + nt) * 32 + lane];
            uint32_t bh1 = sW[(1 * 8 + nt) * 32 + lane];
            uint32_t bl0 = sW[512 + (0 * 8 + nt) * 32 + lane];
            uint32_t bl1 = sW[512 + (1 * 8 + nt) * 32 + lane];
            mma_bf16(acc[nt], ah0, ah1, ah2, ah3, bh0, bh1);
            mma_bf16(acc[nt], ah0, ah1, ah2, ah3, bl0, bl1);
            mma_bf16(acc[nt], al0, al1, al2, al3, bh0, bh1);
        }
    }

    int r0 = row0 + w * 16 + grp;
    int r1 = r0 + 8;
    #pragma unroll
    for (int nt = 0; nt < 8; nt++) {
        int col = nt * 8 + q * 2;
        if (r0 < Nn) *(float2*)&g_h1[(size_t)r0 * HID + col] = make_float2(acc[nt][0], acc[nt][1]);
        if (r1 < Nn) *(float2*)&g_h1[(size_t)r1 * HID + col] = make_float2(acc[nt][2], acc[nt][3]);
        float2 a_s = *(const float2*)&att_s[col];
        float2 a_d = *(const float2*)&att_d[col];
        float p0s = acc[nt][0] * a_s.x + acc[nt][1] * a_s.y;
        float p0d = acc[nt][0] * a_d.x + acc[nt][1] * a_d.y;
        float p1s = acc[nt][2] * a_s.x + acc[nt][3] * a_s.y;
        float p1d = acc[nt][2] * a_d.x + acc[nt][3] * a_d.y;
        p0s += __shfl_xor_sync(0xffffffffu, p0s, 1);
        p0s += __shfl_xor_sync(0xffffffffu, p0s, 2);
        p0d += __shfl_xor_sync(0xffffffffu, p0d, 1);
        p0d += __shfl_xor_sync(0xffffffffu, p0d, 2);
        p1s += __shfl_xor_sync(0xffffffffu, p1s, 1);
        p1s += __shfl_xor_sync(0xffffffffu, p1s, 2);
        p1d += __shfl_xor_sync(0xffffffffu, p1d, 1);
        p1d += __shfl_xor_sync(0xffffffffu, p1d, 2);
        if (q == 0) {
            if (r0 < Nn) { g_as1[(size_t)r0 * NH1 + nt] = p0s; g_ad1[(size_t)r0 * NH1 + nt] = p0d; }
            if (r1 < Nn) { g_as1[(size_t)r1 * NH1 + nt] = p1s; g_ad1[(size_t)r1 * NH1 + nt] = p1d; }
        }
    }
}

// ---------------------------------------------------------------------------
// layer-1 fused softmax+aggregate, single pass. One warp per node.
// ---------------------------------------------------------------------------
__global__ __launch_bounds__(256) void agg1_kernel(const float* __restrict__ bias1, int N) {
    int node = (blockIdx.x * blockDim.x + threadIdx.x) >> 5;
    int lane = threadIdx.x & 31;
    if (node >= N) return;
    int start = g_rowptr[node];
    int deg   = g_rowptr[node + 1] - start;
    int hl = lane & 7;
    int hh = lane >> 2;

    float adv   = g_ad1[(size_t)node * NH1 + hl];
    float selfe = __expf(lrelu(g_as1[(size_t)node * NH1 + hl] + adv));
    float2 hv = *(const float2*)&g_h1[(size_t)node * HID + 2 * lane];

    float ax = 0.f, ay = 0.f;
    float s = 0.f;
    for (int base = 0; base < deg; base += 4) {
        int idx = base + (lane >> 3);
        int j = 0; float wt = 0.f;
        if (idx < deg) {
            j = g_col[start + idx];
            wt = __expf(lrelu(g_as1[(size_t)j * NH1 + hl] + adv));
        }
        s += wt;
        int nb = min(4, deg - base);
        #pragma unroll
        for (int e = 0; e < 4; e++) {
            if (e >= nb) break;
            float we = __shfl_sync(0xffffffffu, wt, e * 8 + hh);
            int je   = __shfl_sync(0xffffffffu, j, e * 8);
            float2 v = *(const float2*)&g_h1[(size_t)je * HID + 2 * lane];
            ax = fmaf(we, v.x, ax);
            ay = fmaf(we, v.y, ay);
        }
    }
    s += __shfl_xor_sync(0xffffffffu, s, 8);
    s += __shfl_xor_sync(0xffffffffu, s, 16);
    s += selfe;
    float inv = 1.f / (s + EPSV);
    float invB   = __shfl_sync(0xffffffffu, inv, hh);
    float selfeB = __shfl_sync(0xffffffffu, selfe, hh);
    ax = (ax + selfeB * hv.x) * invB;
    ay = (ay + selfeB * hv.y) * invB;
    float2 bb = *(const float2*)&bias1[2 * lane];
    ax += bb.x; ay += bb.y;
    ax = ax > 0.f ? ax : (__expf(ax) - 1.f);
    ay = ay > 0.f ? ay : (__expf(ay) - 1.f);
    *(float2*)&g_helu[(size_t)node * HID + 2 * lane] = make_float2(ax, ay);
}

// ---------------------------------------------------------------------------
// layer-2 GEMM (thread per node) + attention scalars
// ---------------------------------------------------------------------------
__global__ __launch_bounds__(256) void gemm2_kernel(const float* __restrict__ W2,
                                                    const float* __restrict__ att_s,
                                                    const float* __restrict__ att_d,
                                                    int N) {
    __shared__ float sW[HID * C2];
    __shared__ float sas[C2], sad[C2];
    int tid = threadIdx.x;
    for (int i = tid; i < HID * C2; i += blockDim.x) sW[i] = W2[i];
    if (tid < C2) { sas[tid] = att_s[tid]; sad[tid] = att_d[tid]; }
    __syncthreads();
    int n = blockIdx.x * blockDim.x + tid;
    if (n >= N) return;
    float acc[C2];
    #pragma unroll
    for (int c = 0; c < C2; c++) acc[c] = 0.f;
    const float* hr = &g_helu[(size_t)n * HID];
    #pragma unroll
    for (int k = 0; k < HID; k += 4) {
        float4 h4 = *(const float4*)&hr[k];
        #pragma unroll
        for (int c = 0; c < C2; c++) {
            acc[c] = fmaf(h4.x, sW[(k + 0) * C2 + c], acc[c]);
            acc[c] = fmaf(h4.y, sW[(k + 1) * C2 + c], acc[c]);
            acc[c] = fmaf(h4.z, sW[(k + 2) * C2 + c], acc[c]);
            acc[c] = fmaf(h4.w, sW[(k + 3) * C2 + c], acc[c]);
        }
    }
    #pragma unroll
    for (int c = 0; c < C2; c += 4)
        *(float4*)&g_y2[(size_t)n * C2 + c] = make_float4(acc[c], acc[c+1], acc[c+2], acc[c+3]);
    float ps = 0.f, pd = 0.f;
    #pragma unroll
    for (int c = 0; c < C2; c++) { ps = fmaf(acc[c], sas[c], ps); pd = fmaf(acc[c], sad[c], pd); }
    g_as2[n] = ps;
    g_ad2[n] = pd;
}

// ---------------------------------------------------------------------------
// layer-2 fused softmax+aggregate, single pass + bias + final softmax
// ---------------------------------------------------------------------------
__global__ __launch_bounds__(256) void agg2_kernel(const float* __restrict__ bias2,
                                                   float* __restrict__ out, int N) {
    int node = (blockIdx.x * blockDim.x + threadIdx.x) >> 5;
    int lane = threadIdx.x & 31;
    if (node >= N) return;
    int start = g_rowptr[node];
    int deg   = g_rowptr[node + 1] - start;

    float ad    = g_ad2[node];
    float selfe = __expf(lrelu(g_as2[node] + ad));
    int c = lane & 15, half = lane >> 4;

    float acc = 0.f;
    float s = 0.f;
    for (int base = 0; base < deg; base += 32) {
        int idx = base + lane;
        int j = 0; float wt = 0.f;
        if (idx < deg) {
            j = g_col[start + idx];
            wt = __expf(lrelu(g_as2[j] + ad));
        }
        s += wt;
        int nb = min(32, deg - base);
        for (int p = 0; p < nb; p += 2) {
            int e = p + half;
            float we = __shfl_sync(0xffffffffu, wt, e & 31);
            int je   = __shfl_sync(0xffffffffu, j, e & 31);
            if (e < nb) acc = fmaf(we, g_y2[(size_t)je * C2 + c], acc);
        }
    }
    #pragma unroll
    for (int d = 16; d >= 1; d >>= 1)
        s += __shfl_xor_sync(0xffffffffu, s, d);
    s += selfe;
    float inv = 1.f / (s + EPSV);

    acc += __shfl_xor_sync(0xffffffffu, acc, 16);
    acc = (acc + selfe * g_y2[(size_t)node * C2 + c]) * inv;
    acc += bias2[c];

    float mx = acc;
    #pragma unroll
    for (int d = 8; d >= 1; d >>= 1)
        mx = fmaxf(mx, __shfl_xor_sync(0xffffffffu, mx, d));
    float p = __expf(acc - mx);
    float ss = p;
    #pragma unroll
    for (int d = 8; d >= 1; d >>= 1)
        ss += __shfl_xor_sync(0xffffffffu, ss, d);
    float soft = p / ss;

    if (lane < 16) {
        out[(size_t)node * C2 + c] = soft;
        out[(size_t)N * C2 + (size_t)node * C2 + c] = acc;
    }
}

// ---------------------------------------------------------------------------
// launch: CSR build (default stream) concurrent with convW+gemm1 (s2),
// with serial fallback if stream/event creation fails.
// ---------------------------------------------------------------------------
extern "C" void kernel_launch(void* const* d_in, const int* in_sizes, int n_in,
                              void* d_out, int out_size) {
    const float* x   = (const float*)d_in[0];
    const void*  ei  = d_in[1];
    const float* W1  = (const float*)d_in[2];
    const float* as1 = (const float*)d_in[3];
    const float* ad1 = (const float*)d_in[4];
    const float* b1  = (const float*)d_in[5];
    const float* W2  = (const float*)d_in[6];
    const float* as2 = (const float*)d_in[7];
    const float* ad2 = (const float*)d_in[8];
    const float* b2  = (const float*)d_in[9];
    float* out = (float*)d_out;

    int E = in_sizes[1] / 2;
    int N = in_sizes[0] / FIN;
    int NB = (N + 1023) / 1024;
    int EB2 = ((E + 1) / 2 + 255) / 256;

    static cudaStream_t s2 = nullptr;
    static cudaEvent_t evFork = nullptr, evJoin = nullptr;
    static int streams_ok = -1;
    if (streams_ok < 0) {
        streams_ok = 1;
        if (cudaStreamCreateWithFlags(&s2, cudaStreamNonBlocking) != cudaSuccess) streams_ok = 0;
        if (streams_ok &&
            cudaEventCreateWithFlags(&evFork, cudaEventDisableTiming) != cudaSuccess) streams_ok = 0;
        if (streams_ok &&
            cudaEventCreateWithFlags(&evJoin, cudaEventDisableTiming) != cudaSuccess) streams_ok = 0;
    }

    if (streams_ok) {
        // fork: side stream runs the GEMM1 chain (independent of edge data)
        cudaEventRecord(evFork, 0);
        cudaStreamWaitEvent(s2, evFork, 0);
        convW_kernel<<<64, 256, 0, s2>>>(W1);
        gemm1_mma_kernel<<<(N + 127) / 128, 256, 0, s2>>>(x, as1, ad1, N);
        cudaEventRecord(evJoin, s2);

        // default stream: CSR build chain
        detect_kernel<<<1, 32>>>((const long long*)ei, N, E);
        count_kernel<<<EB2, 256>>>(ei, E, N);
        scan1_kernel<<<NB, 1024>>>(N);
        scan2_kernel<<<1, 128>>>(NB, N);
        scan3_kernel<<<NB, 1024>>>(N);
        scatter_kernel<<<EB2, 256>>>(ei, E);

        cudaStreamWaitEvent(0, evJoin, 0);
    } else {
        // serial fallback
        detect_kernel<<<1, 32>>>((const long long*)ei, N, E);
        count_kernel<<<EB2, 256>>>(ei, E, N);
        scan1_kernel<<<NB, 1024>>>(N);
        scan2_kernel<<<1, 128>>>(NB, N);
        scan3_kernel<<<NB, 1024>>>(N);
        scatter_kernel<<<EB2, 256>>>(ei, E);
        convW_kernel<<<64, 256>>>(W1);
        gemm1_mma_kernel<<<(N + 127) / 128, 256>>>(x, as1, ad1, N);
    }

    agg1_kernel<<<(N + 7) / 8, 256>>>(b1, N);
    gemm2_kernel<<<(N + 255) / 256, 256>>>(W2, as2, ad2, N);
    agg2_kernel<<<(N + 7) / 8, 256>>>(b2, out, N);
}

// round 12
// speedup vs baseline: 1.0540x; 1.0451x over previous
#include <cuda_runtime.h>
#include <cuda_fp16.h>
#include <cstdint>

// ---------------------------------------------------------------------------
// Problem constants
// ---------------------------------------------------------------------------
#define NMAX 100000
#define EMAX 1600000
#define FIN  512
#define HID  64
#define NH1  8
#define C2   16
#define NEG_SLOPE 0.2f
#define EPSV 1e-16f
#define NCHUNK 32            // K chunks of 16

// ---------------------------------------------------------------------------
// Device scratch
// ---------------------------------------------------------------------------
__device__ float g_h1[(size_t)NMAX * HID];
__device__ float g_helu[(size_t)NMAX * HID];
__device__ float g_y2[(size_t)NMAX * C2];
__device__ float g_as1[(size_t)NMAX * NH1];
__device__ float g_ad1[(size_t)NMAX * NH1];
__device__ float g_as2[NMAX];
__device__ float g_ad2[NMAX];
__device__ int   g_rowptr[NMAX + 1];
__device__ int   g_head[NMAX];
__device__ int   g_cnt[NMAX];          // zero-init at load; scan1 re-zeroes
__device__ int   g_col[EMAX];
__device__ int   g_bsum[128];
__device__ int   g_boff[128];
__device__ int   g_is64;
// W1 pre-converted to mma-fragment-major fp16 hi/lo:
// layout [chunk][ hi(512 words) | lo(512 words) ], word idx = (reg*8+nt)*32+lane
__device__ uint32_t g_wf[NCHUNK * 1024];

__device__ __forceinline__ float lrelu(float v) { return v > 0.f ? v : NEG_SLOPE * v; }

__device__ __forceinline__ void mma_f16(float* c, uint32_t a0, uint32_t a1,
                                        uint32_t a2, uint32_t a3,
                                        uint32_t b0, uint32_t b1) {
    asm("mma.sync.aligned.m16n8k16.row.col.f32.f16.f16.f32 "
        "{%0,%1,%2,%3}, {%4,%5,%6,%7}, {%8,%9}, {%0,%1,%2,%3};"
        : "+f"(c[0]), "+f"(c[1]), "+f"(c[2]), "+f"(c[3])
        : "r"(a0), "r"(a1), "r"(a2), "r"(a3), "r"(b0), "r"(b1));
}

// ---------------------------------------------------------------------------
// edge dtype detection
// ---------------------------------------------------------------------------
__global__ void detect_kernel(const long long* p, int N, int E) {
    if (threadIdx.x == 0 && blockIdx.x == 0) {
        int n = E < 64 ? E : 64;
        int ok = 1;
        for (int i = 0; i < n; i++) {
            long long v = p[i];
            if (v < 0 || v >= (long long)N) { ok = 0; break; }
        }
        g_is64 = ok;
    }
}

// count: 2 edges per thread, vectorized loads of the dst half
__global__ void count_kernel(const void* ei, int E, int N) {
    int t = blockIdx.x * blockDim.x + threadIdx.x;
    int e = t * 2;
    if (e >= E) return;
    int d0, d1;
    if (g_is64) {
        longlong2 v = *(const longlong2*)((const long long*)ei + (size_t)E + e);
        d0 = (int)v.x; d1 = (int)v.y;
    } else {
        int2 v = *(const int2*)((const int*)ei + (size_t)E + e);
        d0 = v.x; d1 = v.y;
    }
    atomicAdd(&g_cnt[d0], 1);
    if (e + 1 < E) atomicAdd(&g_cnt[d1], 1);
}

// ---------------------------------------------------------------------------
// multi-block exclusive scan (scan1 also re-zeroes g_cnt for the next replay)
// ---------------------------------------------------------------------------
__global__ __launch_bounds__(1024) void scan1_kernel(int N) {
    __shared__ int ws[32];
    int tid = threadIdx.x, lane = tid & 31, w = tid >> 5;
    int i = blockIdx.x * 1024 + tid;
    int v = (i < N) ? g_cnt[i] : 0;
    if (i < N) g_cnt[i] = 0;           // reset for next graph replay
    int x = v;
    #pragma unroll
    for (int d = 1; d < 32; d <<= 1) {
        int t = __shfl_up_sync(0xffffffffu, x, d);
        if (lane >= d) x += t;
    }
    if (lane == 31) ws[w] = x;
    __syncthreads();
    if (tid < 32) {
        int s = ws[tid];
        #pragma unroll
        for (int d = 1; d < 32; d <<= 1) {
            int t = __shfl_up_sync(0xffffffffu, s, d);
            if (tid >= d) s += t;
        }
        ws[tid] = s;
    }
    __syncthreads();
    int incl = x + (w > 0 ? ws[w - 1] : 0);
    if (i < N) g_rowptr[i] = incl - v;
    if (tid == 1023) g_bsum[blockIdx.x] = incl;
}

__global__ void scan2_kernel(int NB, int N) {
    __shared__ int ws[4];
    int tid = threadIdx.x, lane = tid & 31, w = tid >> 5;
    int v = (tid < NB) ? g_bsum[tid] : 0;
    int x = v;
    #pragma unroll
    for (int d = 1; d < 32; d <<= 1) {
        int t = __shfl_up_sync(0xffffffffu, x, d);
        if (lane >= d) x += t;
    }
    if (lane == 31) ws[w] = x;
    __syncthreads();
    if (tid < 4) {
        int s = ws[tid];
        for (int d = 1; d < 4; d <<= 1) {
            int t = __shfl_up_sync(0xfu, s, d);
            if (tid >= d) s += t;
        }
        ws[tid] = s;
    }
    __syncthreads();
    int incl = x + (w > 0 ? ws[w - 1] : 0);
    if (tid < NB) g_boff[tid] = incl - v;
    if (tid == NB - 1) g_rowptr[N] = incl;
}

__global__ __launch_bounds__(1024) void scan3_kernel(int N) {
    int i = blockIdx.x * 1024 + threadIdx.x;
    if (i < N) {
        int r = g_rowptr[i] + g_boff[blockIdx.x];
        g_rowptr[i] = r;
        g_head[i] = r;
    }
}

// scatter: 2 edges per thread, vectorized loads
__global__ void scatter_kernel(const void* ei, int E) {
    int t = blockIdx.x * blockDim.x + threadIdx.x;
    int e = t * 2;
    if (e >= E) return;
    int s0, s1, d0, d1;
    if (g_is64) {
        longlong2 sv = *(const longlong2*)((const long long*)ei + e);
        longlong2 dv = *(const longlong2*)((const long long*)ei + (size_t)E + e);
        s0 = (int)sv.x; s1 = (int)sv.y; d0 = (int)dv.x; d1 = (int)dv.y;
    } else {
        int2 sv = *(const int2*)((const int*)ei + e);
        int2 dv = *(const int2*)((const int*)ei + (size_t)E + e);
        s0 = sv.x; s1 = sv.y; d0 = dv.x; d1 = dv.y;
    }
    int p0 = atomicAdd(&g_head[d0], 1);
    g_col[p0] = s0;
    if (e + 1 < E) {
        int p1 = atomicAdd(&g_head[d1], 1);
        g_col[p1] = s1;
    }
}

// ---------------------------------------------------------------------------
// W1 -> fragment-major fp16 hi/lo (2-term split; B residual error ~2^-23)
// ---------------------------------------------------------------------------
__global__ void convW_kernel(const float* __restrict__ W) {
    int t = blockIdx.x * 256 + threadIdx.x;
    if (t >= NCHUNK * 2 * 8 * 32) return;
    int lane = t & 31;
    int nt = (t >> 5) & 7;
    int r  = (t >> 8) & 1;
    int c  = t >> 9;
    int grp = lane >> 2, q = lane & 3;
    int k = c * 16 + r * 8 + q * 2;
    int n = nt * 8 + grp;
    float w0 = W[(size_t)k * HID + n];
    float w1 = W[(size_t)(k + 1) * HID + n];
    __half h0 = __float2half_rn(w0), h1 = __float2half_rn(w1);
    float r0 = w0 - __half2float(h0);
    float r1 = w1 - __half2float(h1);
    __half2 hh; hh.x = h0; hh.y = h1;
    __half2 ll = __floats2half2_rn(r0, r1);
    g_wf[c * 1024 +       (r * 8 + nt) * 32 + lane] = *(uint32_t*)&hh;
    g_wf[c * 1024 + 512 + (r * 8 + nt) * 32 + lane] = *(uint32_t*)&ll;
}

// ---------------------------------------------------------------------------
// GEMM1: h1[N,64] = x[N,512] @ W1 via mma.sync fp16 (A single, B hi/lo, 2 terms)
// 256 threads = 8 warps x 16 rows. Fused attn1 epilogue (head == n-tile).
// APAD=12: row offset in words is a multiple of 4 -> STS.128 aligned; lane
// word (grp*12+q) mod 32 all-distinct -> conflict-free LDS.
// ---------------------------------------------------------------------------
#define APAD 12
__global__ __launch_bounds__(256) void gemm1_mma_kernel(const float* __restrict__ x,
                                                        const float* __restrict__ att_s,
                                                        const float* __restrict__ att_d,
                                                        int Nn) {
    __shared__ uint32_t sA[128 * APAD];    // fp16x2, 8 words used per row
    __shared__ uint32_t sW[1024];          // hi 0..511, lo 512..1023

    int tid = threadIdx.x;
    int w = tid >> 5, lane = tid & 31;
    int grp = lane >> 2, q = lane & 3;
    int row0 = blockIdx.x * 128;

    int arow = tid >> 1;
    int acol8 = (tid & 1) * 8;
    int grow_a = row0 + arow;
    const float* abase = x + (size_t)(grow_a < Nn ? grow_a : (Nn - 1)) * FIN + acol8;

    float acc[8][4];
    #pragma unroll
    for (int nt = 0; nt < 8; nt++)
        #pragma unroll
        for (int i = 0; i < 4; i++) acc[nt][i] = 0.f;

    float4 pa0 = *(const float4*)(abase + 0);
    float4 pa1 = *(const float4*)(abase + 4);
    uint4  pw  = *(const uint4*)&g_wf[0 * 1024 + tid * 4];

    for (int c = 0; c < NCHUNK; c++) {
        __syncthreads();
        {
            // A: 8 floats -> 4 packed fp16x2 (one cvt each), one STS.128
            __half2 q0 = __floats2half2_rn(pa0.x, pa0.y);
            __half2 q1 = __floats2half2_rn(pa0.z, pa0.w);
            __half2 q2 = __floats2half2_rn(pa1.x, pa1.y);
            __half2 q3 = __floats2half2_rn(pa1.z, pa1.w);
            int off = arow * APAD + (tid & 1) * 4;   // multiple of 4 words = 16B
            *(uint4*)&sA[off] = make_uint4(*(uint32_t*)&q0, *(uint32_t*)&q1,
                                           *(uint32_t*)&q2, *(uint32_t*)&q3);
            *(uint4*)&sW[tid * 4] = pw;
        }
        if (c + 1 < NCHUNK) {
            pa0 = *(const float4*)(abase + (c + 1) * 16 + 0);
            pa1 = *(const float4*)(abase + (c + 1) * 16 + 4);
            pw  = *(const uint4*)&g_wf[(c + 1) * 1024 + tid * 4];
        }
        __syncthreads();
        int ab = w * 16;
        uint32_t a0 = sA[(ab + grp) * APAD + q];
        uint32_t a1 = sA[(ab + 8 + grp) * APAD + q];
        uint32_t a2 = sA[(ab + grp) * APAD + 4 + q];
        uint32_t a3 = sA[(ab + 8 + grp) * APAD + 4 + q];
        #pragma unroll
        for (int nt = 0; nt < 8; nt++) {
            uint32_t bh0 = sW[(0 * 8 + nt) * 32 + lane];
            uint32_t bh1 = sW[(1 * 8 + nt) * 32 + lane];
            uint32_t bl0 = sW[512 + (0 * 8 + nt) * 32 + lane];
            uint32_t bl1 = sW[512 + (1 * 8 + nt) * 32 + lane];
            mma_f16(acc[nt], a0, a1, a2, a3, bh0, bh1);
            mma_f16(acc[nt], a0, a1, a2, a3, bl0, bl1);
        }
    }

    // epilogue: store h1 + fused per-head attention dots (head == nt)
    int r0 = row0 + w * 16 + grp;
    int r1 = r0 + 8;
    #pragma unroll
    for (int nt = 0; nt < 8; nt++) {
        int col = nt * 8 + q * 2;
        if (r0 < Nn) *(float2*)&g_h1[(size_t)r0 * HID + col] = make_float2(acc[nt][0], acc[nt][1]);
        if (r1 < Nn) *(float2*)&g_h1[(size_t)r1 * HID + col] = make_float2(acc[nt][2], acc[nt][3]);
        float2 a_s = *(const float2*)&att_s[col];
        float2 a_d = *(const float2*)&att_d[col];
        float p0s = acc[nt][0] * a_s.x + acc[nt][1] * a_s.y;
        float p0d = acc[nt][0] * a_d.x + acc[nt][1] * a_d.y;
        float p1s = acc[nt][2] * a_s.x + acc[nt][3] * a_s.y;
        float p1d = acc[nt][2] * a_d.x + acc[nt][3] * a_d.y;
        p0s += __shfl_xor_sync(0xffffffffu, p0s, 1);
        p0s += __shfl_xor_sync(0xffffffffu, p0s, 2);
        p0d += __shfl_xor_sync(0xffffffffu, p0d, 1);
        p0d += __shfl_xor_sync(0xffffffffu, p0d, 2);
        p1s += __shfl_xor_sync(0xffffffffu, p1s, 1);
        p1s += __shfl_xor_sync(0xffffffffu, p1s, 2);
        p1d += __shfl_xor_sync(0xffffffffu, p1d, 1);
        p1d += __shfl_xor_sync(0xffffffffu, p1d, 2);
        if (q == 0) {
            if (r0 < Nn) { g_as1[(size_t)r0 * NH1 + nt] = p0s; g_ad1[(size_t)r0 * NH1 + nt] = p0d; }
            if (r1 < Nn) { g_as1[(size_t)r1 * NH1 + nt] = p1s; g_ad1[(size_t)r1 * NH1 + nt] = p1d; }
        }
    }
}

// ---------------------------------------------------------------------------
// layer-1 fused softmax+aggregate, single pass. One warp per node.
// ---------------------------------------------------------------------------
__global__ __launch_bounds__(256) void agg1_kernel(const float* __restrict__ bias1, int N) {
    int node = (blockIdx.x * blockDim.x + threadIdx.x) >> 5;
    int lane = threadIdx.x & 31;
    if (node >= N) return;
    int start = g_rowptr[node];
    int deg   = g_rowptr[node + 1] - start;
    int hl = lane & 7;
    int hh = lane >> 2;

    float adv   = g_ad1[(size_t)node * NH1 + hl];
    float selfe = __expf(lrelu(g_as1[(size_t)node * NH1 + hl] + adv));
    float2 hv = *(const float2*)&g_h1[(size_t)node * HID + 2 * lane];

    float ax = 0.f, ay = 0.f;
    float s = 0.f;
    for (int base = 0; base < deg; base += 4) {
        int idx = base + (lane >> 3);
        int j = 0; float wt = 0.f;
        if (idx < deg) {
            j = g_col[start + idx];
            wt = __expf(lrelu(g_as1[(size_t)j * NH1 + hl] + adv));
        }
        s += wt;
        int nb = min(4, deg - base);
        #pragma unroll
        for (int e = 0; e < 4; e++) {
            if (e >= nb) break;
            float we = __shfl_sync(0xffffffffu, wt, e * 8 + hh);
            int je   = __shfl_sync(0xffffffffu, j, e * 8);
            float2 v = *(const float2*)&g_h1[(size_t)je * HID + 2 * lane];
            ax = fmaf(we, v.x, ax);
            ay = fmaf(we, v.y, ay);
        }
    }
    s += __shfl_xor_sync(0xffffffffu, s, 8);
    s += __shfl_xor_sync(0xffffffffu, s, 16);
    s += selfe;
    float inv = 1.f / (s + EPSV);
    float invB   = __shfl_sync(0xffffffffu, inv, hh);
    float selfeB = __shfl_sync(0xffffffffu, selfe, hh);
    ax = (ax + selfeB * hv.x) * invB;
    ay = (ay + selfeB * hv.y) * invB;
    float2 bb = *(const float2*)&bias1[2 * lane];
    ax += bb.x; ay += bb.y;
    ax = ax > 0.f ? ax : (__expf(ax) - 1.f);
    ay = ay > 0.f ? ay : (__expf(ay) - 1.f);
    *(float2*)&g_helu[(size_t)node * HID + 2 * lane] = make_float2(ax, ay);
}

// ---------------------------------------------------------------------------
// layer-2 GEMM (thread per node) + attention scalars
// ---------------------------------------------------------------------------
__global__ __launch_bounds__(256) void gemm2_kernel(const float* __restrict__ W2,
                                                    const float* __restrict__ att_s,
                                                    const float* __restrict__ att_d,
                                                    int N) {
    __shared__ float sW[HID * C2];
    __shared__ float sas[C2], sad[C2];
    int tid = threadIdx.x;
    for (int i = tid; i < HID * C2; i += blockDim.x) sW[i] = W2[i];
    if (tid < C2) { sas[tid] = att_s[tid]; sad[tid] = att_d[tid]; }
    __syncthreads();
    int n = blockIdx.x * blockDim.x + tid;
    if (n >= N) return;
    float acc[C2];
    #pragma unroll
    for (int c = 0; c < C2; c++) acc[c] = 0.f;
    const float* hr = &g_helu[(size_t)n * HID];
    #pragma unroll
    for (int k = 0; k < HID; k += 4) {
        float4 h4 = *(const float4*)&hr[k];
        #pragma unroll
        for (int c = 0; c < C2; c++) {
            acc[c] = fmaf(h4.x, sW[(k + 0) * C2 + c], acc[c]);
            acc[c] = fmaf(h4.y, sW[(k + 1) * C2 + c], acc[c]);
            acc[c] = fmaf(h4.z, sW[(k + 2) * C2 + c], acc[c]);
            acc[c] = fmaf(h4.w, sW[(k + 3) * C2 + c], acc[c]);
        }
    }
    #pragma unroll
    for (int c = 0; c < C2; c += 4)
        *(float4*)&g_y2[(size_t)n * C2 + c] = make_float4(acc[c], acc[c+1], acc[c+2], acc[c+3]);
    float ps = 0.f, pd = 0.f;
    #pragma unroll
    for (int c = 0; c < C2; c++) { ps = fmaf(acc[c], sas[c], ps); pd = fmaf(acc[c], sad[c], pd); }
    g_as2[n] = ps;
    g_ad2[n] = pd;
}

// ---------------------------------------------------------------------------
// layer-2 fused softmax+aggregate, single pass + bias + final softmax
// ---------------------------------------------------------------------------
__global__ __launch_bounds__(256) void agg2_kernel(const float* __restrict__ bias2,
                                                   float* __restrict__ out, int N) {
    int node = (blockIdx.x * blockDim.x + threadIdx.x) >> 5;
    int lane = threadIdx.x & 31;
    if (node >= N) return;
    int start = g_rowptr[node];
    int deg   = g_rowptr[node + 1] - start;

    float ad    = g_ad2[node];
    float selfe = __expf(lrelu(g_as2[node] + ad));
    int c = lane & 15, half = lane >> 4;

    float acc = 0.f;
    float s = 0.f;
    for (int base = 0; base < deg; base += 32) {
        int idx = base + lane;
        int j = 0; float wt = 0.f;
        if (idx < deg) {
            j = g_col[start + idx];
            wt = __expf(lrelu(g_as2[j] + ad));
        }
        s += wt;
        int nb = min(32, deg - base);
        for (int p = 0; p < nb; p += 2) {
            int e = p + half;
            float we = __shfl_sync(0xffffffffu, wt, e & 31);
            int je   = __shfl_sync(0xffffffffu, j, e & 31);
            if (e < nb) acc = fmaf(we, g_y2[(size_t)je * C2 + c], acc);
        }
    }
    #pragma unroll
    for (int d = 16; d >= 1; d >>= 1)
        s += __shfl_xor_sync(0xffffffffu, s, d);
    s += selfe;
    float inv = 1.f / (s + EPSV);

    acc += __shfl_xor_sync(0xffffffffu, acc, 16);
    acc = (acc + selfe * g_y2[(size_t)node * C2 + c]) * inv;
    acc += bias2[c];

    float mx = acc;
    #pragma unroll
    for (int d = 8; d >= 1; d >>= 1)
        mx = fmaxf(mx, __shfl_xor_sync(0xffffffffu, mx, d));
    float p = __expf(acc - mx);
    float ss = p;
    #pragma unroll
    for (int d = 8; d >= 1; d >>= 1)
        ss += __shfl_xor_sync(0xffffffffu, ss, d);
    float soft = p / ss;

    if (lane < 16) {
        out[(size_t)node * C2 + c] = soft;
        out[(size_t)N * C2 + (size_t)node * C2 + c] = acc;
    }
}

// ---------------------------------------------------------------------------
// launch: CSR build (default stream) concurrent with convW+gemm1 (s2),
// with serial fallback if stream/event creation fails.
// ---------------------------------------------------------------------------
extern "C" void kernel_launch(void* const* d_in, const int* in_sizes, int n_in,
                              void* d_out, int out_size) {
    const float* x   = (const float*)d_in[0];
    const void*  ei  = d_in[1];
    const float* W1  = (const float*)d_in[2];
    const float* as1 = (const float*)d_in[3];
    const float* ad1 = (const float*)d_in[4];
    const float* b1  = (const float*)d_in[5];
    const float* W2  = (const float*)d_in[6];
    const float* as2 = (const float*)d_in[7];
    const float* ad2 = (const float*)d_in[8];
    const float* b2  = (const float*)d_in[9];
    float* out = (float*)d_out;

    int E = in_sizes[1] / 2;
    int N = in_sizes[0] / FIN;
    int NB = (N + 1023) / 1024;
    int EB2 = ((E + 1) / 2 + 255) / 256;

    static cudaStream_t s2 = nullptr;
    static cudaEvent_t evFork = nullptr, evJoin = nullptr;
    static int streams_ok = -1;
    if (streams_ok < 0) {
        streams_ok = 1;
        if (cudaStreamCreateWithFlags(&s2, cudaStreamNonBlocking) != cudaSuccess) streams_ok = 0;
        if (streams_ok &&
            cudaEventCreateWithFlags(&evFork, cudaEventDisableTiming) != cudaSuccess) streams_ok = 0;
        if (streams_ok &&
            cudaEventCreateWithFlags(&evJoin, cudaEventDisableTiming) != cudaSuccess) streams_ok = 0;
    }

    if (streams_ok) {
        // fork: side stream runs the GEMM1 chain (independent of edge data)
        cudaEventRecord(evFork, 0);
        cudaStreamWaitEvent(s2, evFork, 0);
        convW_kernel<<<64, 256, 0, s2>>>(W1);
        gemm1_mma_kernel<<<(N + 127) / 128, 256, 0, s2>>>(x, as1, ad1, N);
        cudaEventRecord(evJoin, s2);

        // default stream: CSR build chain
        detect_kernel<<<1, 32>>>((const long long*)ei, N, E);
        count_kernel<<<EB2, 256>>>(ei, E, N);
        scan1_kernel<<<NB, 1024>>>(N);
        scan2_kernel<<<1, 128>>>(NB, N);
        scan3_kernel<<<NB, 1024>>>(N);
        scatter_kernel<<<EB2, 256>>>(ei, E);

        cudaStreamWaitEvent(0, evJoin, 0);
    } else {
        // serial fallback
        detect_kernel<<<1, 32>>>((const long long*)ei, N, E);
        count_kernel<<<EB2, 256>>>(ei, E, N);
        scan1_kernel<<<NB, 1024>>>(N);
        scan2_kernel<<<1, 128>>>(NB, N);
        scan3_kernel<<<NB, 1024>>>(N);
        scatter_kernel<<<EB2, 256>>>(ei, E);
        convW_kernel<<<64, 256>>>(W1);
        gemm1_mma_kernel<<<(N + 127) / 128, 256>>>(x, as1, ad1, N);
    }

    agg1_kernel<<<(N + 7) / 8, 256>>>(b1, N);
    gemm2_kernel<<<(N + 255) / 256, 256>>>(W2, as2, ad2, N);
    agg2_kernel<<<(N + 7) / 8, 256>>>(b2, out, N);
}

// round 13
// speedup vs baseline: 1.2228x; 1.1602x over previous
#include <cuda_runtime.h>
#include <cuda_fp16.h>
#include <cstdint>

// ---------------------------------------------------------------------------
// Problem constants
// ---------------------------------------------------------------------------
#define NMAX 100000
#define EMAX 1600000
#define FIN  512
#define HID  64
#define NH1  8
#define C2   16
#define NEG_SLOPE 0.2f
#define EPSV 1e-16f
#define NCHUNK 32            // K chunks of 16

// ---------------------------------------------------------------------------
// Device scratch
// ---------------------------------------------------------------------------
__device__ uint32_t g_h1h[(size_t)NMAX * 32];   // h1 packed fp16x2 (cols 2w,2w+1)
__device__ float g_helu[(size_t)NMAX * HID];
__device__ float g_y2[(size_t)NMAX * C2];
__device__ float g_as1[(size_t)NMAX * NH1];
__device__ float g_ad1[(size_t)NMAX * NH1];
__device__ float g_as2[NMAX];
__device__ float g_ad2[NMAX];
__device__ int   g_rowptr[NMAX + 1];
__device__ int   g_head[NMAX];
__device__ int   g_cnt[NMAX];          // zero-init at load; scan1 re-zeroes
__device__ int   g_col[EMAX];
__device__ int   g_bsum[128];
__device__ int   g_boff[128];
__device__ int   g_is64;
// W1 pre-converted to mma-fragment-major fp16 (hi only used):
// layout [chunk][ hi(512 words) | lo(512 words, unused) ]
__device__ uint32_t g_wf[NCHUNK * 1024];

__device__ __forceinline__ float lrelu(float v) { return v > 0.f ? v : NEG_SLOPE * v; }

__device__ __forceinline__ void mma_f16(float* c, uint32_t a0, uint32_t a1,
                                        uint32_t a2, uint32_t a3,
                                        uint32_t b0, uint32_t b1) {
    asm("mma.sync.aligned.m16n8k16.row.col.f32.f16.f16.f32 "
        "{%0,%1,%2,%3}, {%4,%5,%6,%7}, {%8,%9}, {%0,%1,%2,%3};"
        : "+f"(c[0]), "+f"(c[1]), "+f"(c[2]), "+f"(c[3])
        : "r"(a0), "r"(a1), "r"(a2), "r"(a3), "r"(b0), "r"(b1));
}

// ---------------------------------------------------------------------------
// edge dtype detection
// ---------------------------------------------------------------------------
__global__ void detect_kernel(const long long* p, int N, int E) {
    if (threadIdx.x == 0 && blockIdx.x == 0) {
        int n = E < 64 ? E : 64;
        int ok = 1;
        for (int i = 0; i < n; i++) {
            long long v = p[i];
            if (v < 0 || v >= (long long)N) { ok = 0; break; }
        }
        g_is64 = ok;
    }
}

// count: 2 edges per thread, vectorized loads of the dst half
__global__ void count_kernel(const void* ei, int E, int N) {
    int t = blockIdx.x * blockDim.x + threadIdx.x;
    int e = t * 2;
    if (e >= E) return;
    int d0, d1;
    if (g_is64) {
        longlong2 v = *(const longlong2*)((const long long*)ei + (size_t)E + e);
        d0 = (int)v.x; d1 = (int)v.y;
    } else {
        int2 v = *(const int2*)((const int*)ei + (size_t)E + e);
        d0 = v.x; d1 = v.y;
    }
    atomicAdd(&g_cnt[d0], 1);
    if (e + 1 < E) atomicAdd(&g_cnt[d1], 1);
}

// ---------------------------------------------------------------------------
// multi-block exclusive scan (scan1 also re-zeroes g_cnt for the next replay)
// ---------------------------------------------------------------------------
__global__ __launch_bounds__(1024) void scan1_kernel(int N) {
    __shared__ int ws[32];
    int tid = threadIdx.x, lane = tid & 31, w = tid >> 5;
    int i = blockIdx.x * 1024 + tid;
    int v = (i < N) ? g_cnt[i] : 0;
    if (i < N) g_cnt[i] = 0;           // reset for next graph replay
    int x = v;
    #pragma unroll
    for (int d = 1; d < 32; d <<= 1) {
        int t = __shfl_up_sync(0xffffffffu, x, d);
        if (lane >= d) x += t;
    }
    if (lane == 31) ws[w] = x;
    __syncthreads();
    if (tid < 32) {
        int s = ws[tid];
        #pragma unroll
        for (int d = 1; d < 32; d <<= 1) {
            int t = __shfl_up_sync(0xffffffffu, s, d);
            if (tid >= d) s += t;
        }
        ws[tid] = s;
    }
    __syncthreads();
    int incl = x + (w > 0 ? ws[w - 1] : 0);
    if (i < N) g_rowptr[i] = incl - v;
    if (tid == 1023) g_bsum[blockIdx.x] = incl;
}

__global__ void scan2_kernel(int NB, int N) {
    __shared__ int ws[4];
    int tid = threadIdx.x, lane = tid & 31, w = tid >> 5;
    int v = (tid < NB) ? g_bsum[tid] : 0;
    int x = v;
    #pragma unroll
    for (int d = 1; d < 32; d <<= 1) {
        int t = __shfl_up_sync(0xffffffffu, x, d);
        if (lane >= d) x += t;
    }
    if (lane == 31) ws[w] = x;
    __syncthreads();
    if (tid < 4) {
        int s = ws[tid];
        for (int d = 1; d < 4; d <<= 1) {
            int t = __shfl_up_sync(0xfu, s, d);
            if (tid >= d) s += t;
        }
        ws[tid] = s;
    }
    __syncthreads();
    int incl = x + (w > 0 ? ws[w - 1] : 0);
    if (tid < NB) g_boff[tid] = incl - v;
    if (tid == NB - 1) g_rowptr[N] = incl;
}

__global__ __launch_bounds__(1024) void scan3_kernel(int N) {
    int i = blockIdx.x * 1024 + threadIdx.x;
    if (i < N) {
        int r = g_rowptr[i] + g_boff[blockIdx.x];
        g_rowptr[i] = r;
        g_head[i] = r;
    }
}

// scatter: 2 edges per thread, vectorized loads
__global__ void scatter_kernel(const void* ei, int E) {
    int t = blockIdx.x * blockDim.x + threadIdx.x;
    int e = t * 2;
    if (e >= E) return;
    int s0, s1, d0, d1;
    if (g_is64) {
        longlong2 sv = *(const longlong2*)((const long long*)ei + e);
        longlong2 dv = *(const longlong2*)((const long long*)ei + (size_t)E + e);
        s0 = (int)sv.x; s1 = (int)sv.y; d0 = (int)dv.x; d1 = (int)dv.y;
    } else {
        int2 sv = *(const int2*)((const int*)ei + e);
        int2 dv = *(const int2*)((const int*)ei + (size_t)E + e);
        s0 = sv.x; s1 = sv.y; d0 = dv.x; d1 = dv.y;
    }
    int p0 = atomicAdd(&g_head[d0], 1);
    g_col[p0] = s0;
    if (e + 1 < E) {
        int p1 = atomicAdd(&g_head[d1], 1);
        g_col[p1] = s1;
    }
}

// ---------------------------------------------------------------------------
// W1 -> fragment-major fp16 (hi used by GEMM; lo kept but unused)
// ---------------------------------------------------------------------------
__global__ void convW_kernel(const float* __restrict__ W) {
    int t = blockIdx.x * 256 + threadIdx.x;
    if (t >= NCHUNK * 2 * 8 * 32) return;
    int lane = t & 31;
    int nt = (t >> 5) & 7;
    int r  = (t >> 8) & 1;
    int c  = t >> 9;
    int grp = lane >> 2, q = lane & 3;
    int k = c * 16 + r * 8 + q * 2;
    int n = nt * 8 + grp;
    float w0 = W[(size_t)k * HID + n];
    float w1 = W[(size_t)(k + 1) * HID + n];
    __half2 hh = __floats2half2_rn(w0, w1);
    g_wf[c * 1024 + (r * 8 + nt) * 32 + lane] = *(uint32_t*)&hh;
}

// ---------------------------------------------------------------------------
// GEMM1: h1[N,64] = x[N,512] @ W1 via mma.sync fp16 (single A, single B,
// 8 MMAs/chunk). 256 threads = 8 warps x 16 rows. Fused attn1 epilogue.
// APAD=12: STS.128 aligned, conflict-free fragment LDS.
// ---------------------------------------------------------------------------
#define APAD 12
__global__ __launch_bounds__(256) void gemm1_mma_kernel(const float* __restrict__ x,
                                                        const float* __restrict__ att_s,
                                                        const float* __restrict__ att_d,
                                                        int Nn) {
    __shared__ uint32_t sA[128 * APAD];    // fp16x2, 8 words used per row
    __shared__ uint32_t sW[512];           // hi fragments only

    int tid = threadIdx.x;
    int w = tid >> 5, lane = tid & 31;
    int grp = lane >> 2, q = lane & 3;
    int row0 = blockIdx.x * 128;

    int arow = tid >> 1;
    int acol8 = (tid & 1) * 8;
    int grow_a = row0 + arow;
    const float* abase = x + (size_t)(grow_a < Nn ? grow_a : (Nn - 1)) * FIN + acol8;

    float acc[8][4];
    #pragma unroll
    for (int nt = 0; nt < 8; nt++)
        #pragma unroll
        for (int i = 0; i < 4; i++) acc[nt][i] = 0.f;

    float4 pa0 = *(const float4*)(abase + 0);
    float4 pa1 = *(const float4*)(abase + 4);
    uint2  pw  = *(const uint2*)&g_wf[0 * 1024 + tid * 2];

    for (int c = 0; c < NCHUNK; c++) {
        __syncthreads();
        {
            __half2 q0 = __floats2half2_rn(pa0.x, pa0.y);
            __half2 q1 = __floats2half2_rn(pa0.z, pa0.w);
            __half2 q2 = __floats2half2_rn(pa1.x, pa1.y);
            __half2 q3 = __floats2half2_rn(pa1.z, pa1.w);
            int off = arow * APAD + (tid & 1) * 4;   // multiple of 4 words = 16B
            *(uint4*)&sA[off] = make_uint4(*(uint32_t*)&q0, *(uint32_t*)&q1,
                                           *(uint32_t*)&q2, *(uint32_t*)&q3);
            *(uint2*)&sW[tid * 2] = pw;
        }
        if (c + 1 < NCHUNK) {
            pa0 = *(const float4*)(abase + (c + 1) * 16 + 0);
            pa1 = *(const float4*)(abase + (c + 1) * 16 + 4);
            pw  = *(const uint2*)&g_wf[(c + 1) * 1024 + tid * 2];
        }
        __syncthreads();
        int ab = w * 16;
        uint32_t a0 = sA[(ab + grp) * APAD + q];
        uint32_t a1 = sA[(ab + 8 + grp) * APAD + q];
        uint32_t a2 = sA[(ab + grp) * APAD + 4 + q];
        uint32_t a3 = sA[(ab + 8 + grp) * APAD + 4 + q];
        #pragma unroll
        for (int nt = 0; nt < 8; nt++) {
            uint32_t b0 = sW[(0 * 8 + nt) * 32 + lane];
            uint32_t b1 = sW[(1 * 8 + nt) * 32 + lane];
            mma_f16(acc[nt], a0, a1, a2, a3, b0, b1);
        }
    }

    // epilogue: store h1 (packed fp16x2) + fused per-head attention dots
    int r0 = row0 + w * 16 + grp;
    int r1 = r0 + 8;
    #pragma unroll
    for (int nt = 0; nt < 8; nt++) {
        int col = nt * 8 + q * 2;
        int wordi = nt * 4 + q;            // col/2
        if (r0 < Nn) {
            __half2 hp = __floats2half2_rn(acc[nt][0], acc[nt][1]);
            g_h1h[(size_t)r0 * 32 + wordi] = *(uint32_t*)&hp;
        }
        if (r1 < Nn) {
            __half2 hp = __floats2half2_rn(acc[nt][2], acc[nt][3]);
            g_h1h[(size_t)r1 * 32 + wordi] = *(uint32_t*)&hp;
        }
        float2 a_s = *(const float2*)&att_s[col];
        float2 a_d = *(const float2*)&att_d[col];
        float p0s = acc[nt][0] * a_s.x + acc[nt][1] * a_s.y;
        float p0d = acc[nt][0] * a_d.x + acc[nt][1] * a_d.y;
        float p1s = acc[nt][2] * a_s.x + acc[nt][3] * a_s.y;
        float p1d = acc[nt][2] * a_d.x + acc[nt][3] * a_d.y;
        p0s += __shfl_xor_sync(0xffffffffu, p0s, 1);
        p0s += __shfl_xor_sync(0xffffffffu, p0s, 2);
        p0d += __shfl_xor_sync(0xffffffffu, p0d, 1);
        p0d += __shfl_xor_sync(0xffffffffu, p0d, 2);
        p1s += __shfl_xor_sync(0xffffffffu, p1s, 1);
        p1s += __shfl_xor_sync(0xffffffffu, p1s, 2);
        p1d += __shfl_xor_sync(0xffffffffu, p1d, 1);
        p1d += __shfl_xor_sync(0xffffffffu, p1d, 2);
        if (q == 0) {
            if (r0 < Nn) { g_as1[(size_t)r0 * NH1 + nt] = p0s; g_ad1[(size_t)r0 * NH1 + nt] = p0d; }
            if (r1 < Nn) { g_as1[(size_t)r1 * NH1 + nt] = p1s; g_ad1[(size_t)r1 * NH1 + nt] = p1d; }
        }
    }
}

// ---------------------------------------------------------------------------
// layer-1 fused softmax+aggregate, single pass. One warp per node.
// h1 is packed fp16x2: lane loads ONE 32-bit word (cols 2l, 2l+1) ->
// a full edge gather is exactly one 128-byte line.
// ---------------------------------------------------------------------------
__global__ __launch_bounds__(256) void agg1_kernel(const float* __restrict__ bias1, int N) {
    int node = (blockIdx.x * blockDim.x + threadIdx.x) >> 5;
    int lane = threadIdx.x & 31;
    if (node >= N) return;
    int start = g_rowptr[node];
    int deg   = g_rowptr[node + 1] - start;
    int hl = lane & 7;
    int hh = lane >> 2;

    float adv   = g_ad1[(size_t)node * NH1 + hl];
    float selfe = __expf(lrelu(g_as1[(size_t)node * NH1 + hl] + adv));
    uint32_t hw = g_h1h[(size_t)node * 32 + lane];
    float2 hv = __half22float2(*(__half2*)&hw);

    float ax = 0.f, ay = 0.f;
    float s = 0.f;
    for (int base = 0; base < deg; base += 4) {
        int idx = base + (lane >> 3);
        int j = 0; float wt = 0.f;
        if (idx < deg) {
            j = g_col[start + idx];
            wt = __expf(lrelu(g_as1[(size_t)j * NH1 + hl] + adv));
        }
        s += wt;
        int nb = min(4, deg - base);
        #pragma unroll
        for (int e = 0; e < 4; e++) {
            if (e >= nb) break;
            float we = __shfl_sync(0xffffffffu, wt, e * 8 + hh);
            int je   = __shfl_sync(0xffffffffu, j, e * 8);
            uint32_t vw = g_h1h[(size_t)je * 32 + lane];
            float2 v = __half22float2(*(__half2*)&vw);
            ax = fmaf(we, v.x, ax);
            ay = fmaf(we, v.y, ay);
        }
    }
    s += __shfl_xor_sync(0xffffffffu, s, 8);
    s += __shfl_xor_sync(0xffffffffu, s, 16);
    s += selfe;
    float inv = 1.f / (s + EPSV);
    float invB   = __shfl_sync(0xffffffffu, inv, hh);
    float selfeB = __shfl_sync(0xffffffffu, selfe, hh);
    ax = (ax + selfeB * hv.x) * invB;
    ay = (ay + selfeB * hv.y) * invB;
    float2 bb = *(const float2*)&bias1[2 * lane];
    ax += bb.x; ay += bb.y;
    ax = ax > 0.f ? ax : (__expf(ax) - 1.f);
    ay = ay > 0.f ? ay : (__expf(ay) - 1.f);
    *(float2*)&g_helu[(size_t)node * HID + 2 * lane] = make_float2(ax, ay);
}

// ---------------------------------------------------------------------------
// layer-2 GEMM (thread per node) + attention scalars
// ---------------------------------------------------------------------------
__global__ __launch_bounds__(256) void gemm2_kernel(const float* __restrict__ W2,
                                                    const float* __restrict__ att_s,
                                                    const float* __restrict__ att_d,
                                                    int N) {
    __shared__ float sW[HID * C2];
    __shared__ float sas[C2], sad[C2];
    int tid = threadIdx.x;
    for (int i = tid; i < HID * C2; i += blockDim.x) sW[i] = W2[i];
    if (tid < C2) { sas[tid] = att_s[tid]; sad[tid] = att_d[tid]; }
    __syncthreads();
    int n = blockIdx.x * blockDim.x + tid;
    if (n >= N) return;
    float acc[C2];
    #pragma unroll
    for (int c = 0; c < C2; c++) acc[c] = 0.f;
    const float* hr = &g_helu[(size_t)n * HID];
    #pragma unroll
    for (int k = 0; k < HID; k += 4) {
        float4 h4 = *(const float4*)&hr[k];
        #pragma unroll
        for (int c = 0; c < C2; c++) {
            acc[c] = fmaf(h4.x, sW[(k + 0) * C2 + c], acc[c]);
            acc[c] = fmaf(h4.y, sW[(k + 1) * C2 + c], acc[c]);
            acc[c] = fmaf(h4.z, sW[(k + 2) * C2 + c], acc[c]);
            acc[c] = fmaf(h4.w, sW[(k + 3) * C2 + c], acc[c]);
        }
    }
    #pragma unroll
    for (int c = 0; c < C2; c += 4)
        *(float4*)&g_y2[(size_t)n * C2 + c] = make_float4(acc[c], acc[c+1], acc[c+2], acc[c+3]);
    float ps = 0.f, pd = 0.f;
    #pragma unroll
    for (int c = 0; c < C2; c++) { ps = fmaf(acc[c], sas[c], ps); pd = fmaf(acc[c], sad[c], pd); }
    g_as2[n] = ps;
    g_ad2[n] = pd;
}

// ---------------------------------------------------------------------------
// layer-2 fused softmax+aggregate, single pass + bias + final softmax
// ---------------------------------------------------------------------------
__global__ __launch_bounds__(256) void agg2_kernel(const float* __restrict__ bias2,
                                                   float* __restrict__ out, int N) {
    int node = (blockIdx.x * blockDim.x + threadIdx.x) >> 5;
    int lane = threadIdx.x & 31;
    if (node >= N) return;
    int start = g_rowptr[node];
    int deg   = g_rowptr[node + 1] - start;

    float ad    = g_ad2[node];
    float selfe = __expf(lrelu(g_as2[node] + ad));
    int c = lane & 15, half = lane >> 4;

    float acc = 0.f;
    float s = 0.f;
    for (int base = 0; base < deg; base += 32) {
        int idx = base + lane;
        int j = 0; float wt = 0.f;
        if (idx < deg) {
            j = g_col[start + idx];
            wt = __expf(lrelu(g_as2[j] + ad));
        }
        s += wt;
        int nb = min(32, deg - base);
        for (int p = 0; p < nb; p += 2) {
            int e = p + half;
            float we = __shfl_sync(0xffffffffu, wt, e & 31);
            int je   = __shfl_sync(0xffffffffu, j, e & 31);
            if (e < nb) acc = fmaf(we, g_y2[(size_t)je * C2 + c], acc);
        }
    }
    #pragma unroll
    for (int d = 16; d >= 1; d >>= 1)
        s += __shfl_xor_sync(0xffffffffu, s, d);
    s += selfe;
    float inv = 1.f / (s + EPSV);

    acc += __shfl_xor_sync(0xffffffffu, acc, 16);
    acc = (acc + selfe * g_y2[(size_t)node * C2 + c]) * inv;
    acc += bias2[c];

    float mx = acc;
    #pragma unroll
    for (int d = 8; d >= 1; d >>= 1)
        mx = fmaxf(mx, __shfl_xor_sync(0xffffffffu, mx, d));
    float p = __expf(acc - mx);
    float ss = p;
    #pragma unroll
    for (int d = 8; d >= 1; d >>= 1)
        ss += __shfl_xor_sync(0xffffffffu, ss, d);
    float soft = p / ss;

    if (lane < 16) {
        out[(size_t)node * C2 + c] = soft;
        out[(size_t)N * C2 + (size_t)node * C2 + c] = acc;
    }
}

// ---------------------------------------------------------------------------
// launch: CSR build (default stream) concurrent with convW+gemm1 (s2),
// with serial fallback if stream/event creation fails.
// ---------------------------------------------------------------------------
extern "C" void kernel_launch(void* const* d_in, const int* in_sizes, int n_in,
                              void* d_out, int out_size) {
    const float* x   = (const float*)d_in[0];
    const void*  ei  = d_in[1];
    const float* W1  = (const float*)d_in[2];
    const float* as1 = (const float*)d_in[3];
    const float* ad1 = (const float*)d_in[4];
    const float* b1  = (const float*)d_in[5];
    const float* W2  = (const float*)d_in[6];
    const float* as2 = (const float*)d_in[7];
    const float* ad2 = (const float*)d_in[8];
    const float* b2  = (const float*)d_in[9];
    float* out = (float*)d_out;

    int E = in_sizes[1] / 2;
    int N = in_sizes[0] / FIN;
    int NB = (N + 1023) / 1024;
    int EB2 = ((E + 1) / 2 + 255) / 256;

    static cudaStream_t s2 = nullptr;
    static cudaEvent_t evFork = nullptr, evJoin = nullptr;
    static int streams_ok = -1;
    if (streams_ok < 0) {
        streams_ok = 1;
        if (cudaStreamCreateWithFlags(&s2, cudaStreamNonBlocking) != cudaSuccess) streams_ok = 0;
        if (streams_ok &&
            cudaEventCreateWithFlags(&evFork, cudaEventDisableTiming) != cudaSuccess) streams_ok = 0;
        if (streams_ok &&
            cudaEventCreateWithFlags(&evJoin, cudaEventDisableTiming) != cudaSuccess) streams_ok = 0;
    }

    if (streams_ok) {
        // fork: side stream runs the GEMM1 chain (independent of edge data)
        cudaEventRecord(evFork, 0);
        cudaStreamWaitEvent(s2, evFork, 0);
        convW_kernel<<<64, 256, 0, s2>>>(W1);
        gemm1_mma_kernel<<<(N + 127) / 128, 256, 0, s2>>>(x, as1, ad1, N);
        cudaEventRecord(evJoin, s2);

        // default stream: CSR build chain
        detect_kernel<<<1, 32>>>((const long long*)ei, N, E);
        count_kernel<<<EB2, 256>>>(ei, E, N);
        scan1_kernel<<<NB, 1024>>>(N);
        scan2_kernel<<<1, 128>>>(NB, N);
        scan3_kernel<<<NB, 1024>>>(N);
        scatter_kernel<<<EB2, 256>>>(ei, E);

        cudaStreamWaitEvent(0, evJoin, 0);
    } else {
        // serial fallback
        detect_kernel<<<1, 32>>>((const long long*)ei, N, E);
        count_kernel<<<EB2, 256>>>(ei, E, N);
        scan1_kernel<<<NB, 1024>>>(N);
        scan2_kernel<<<1, 128>>>(NB, N);
        scan3_kernel<<<NB, 1024>>>(N);
        scatter_kernel<<<EB2, 256>>>(ei, E);
        convW_kernel<<<64, 256>>>(W1);
        gemm1_mma_kernel<<<(N + 127) / 128, 256>>>(x, as1, ad1, N);
    }

    agg1_kernel<<<(N + 7) / 8, 256>>>(b1, N);
    gemm2_kernel<<<(N + 255) / 256, 256>>>(W2, as2, ad2, N);
    agg2_kernel<<<(N + 7) / 8, 256>>>(b2, out, N);
}

// round 14
// speedup vs baseline: 1.2231x; 1.0003x over previous
#include <cuda_runtime.h>
#include <cuda_fp16.h>
#include <cstdint>

// ---------------------------------------------------------------------------
// Problem constants
// ---------------------------------------------------------------------------
#define NMAX 100000
#define EMAX 1600000
#define FIN  512
#define HID  64
#define NH1  8
#define C2   16
#define NEG_SLOPE 0.2f
#define EPSV 1e-16f
#define NCHUNK 32            // K chunks of 16 (GEMM processes 2 per iteration)

// ---------------------------------------------------------------------------
// Device scratch
// ---------------------------------------------------------------------------
__device__ uint32_t g_h1h[(size_t)NMAX * 32];   // h1 packed fp16x2 (cols 2w,2w+1)
__device__ float g_helu[(size_t)NMAX * HID];
__device__ float g_y2[(size_t)NMAX * C2];
__device__ float g_as1[(size_t)NMAX * NH1];
__device__ float g_ad1[(size_t)NMAX * NH1];
__device__ float g_as2[NMAX];
__device__ float g_ad2[NMAX];
__device__ int   g_rowptr[NMAX + 1];
__device__ int   g_head[NMAX];
__device__ int   g_cnt[NMAX];          // zero-init at load; scan1 re-zeroes
__device__ int   g_col[EMAX];
__device__ int   g_bsum[128];
__device__ int   g_boff[128];
__device__ int   g_is64;
// W1 pre-converted to mma-fragment-major fp16 (hi only used):
// layout [chunk][ hi(512 words) | lo(512 words, unused) ]
__device__ uint32_t g_wf[NCHUNK * 1024];

__device__ __forceinline__ float lrelu(float v) { return v > 0.f ? v : NEG_SLOPE * v; }

__device__ __forceinline__ void mma_f16(float* c, uint32_t a0, uint32_t a1,
                                        uint32_t a2, uint32_t a3,
                                        uint32_t b0, uint32_t b1) {
    asm("mma.sync.aligned.m16n8k16.row.col.f32.f16.f16.f32 "
        "{%0,%1,%2,%3}, {%4,%5,%6,%7}, {%8,%9}, {%0,%1,%2,%3};"
        : "+f"(c[0]), "+f"(c[1]), "+f"(c[2]), "+f"(c[3])
        : "r"(a0), "r"(a1), "r"(a2), "r"(a3), "r"(b0), "r"(b1));
}

// ---------------------------------------------------------------------------
// edge dtype detection
// ---------------------------------------------------------------------------
__global__ void detect_kernel(const long long* p, int N, int E) {
    if (threadIdx.x == 0 && blockIdx.x == 0) {
        int n = E < 64 ? E : 64;
        int ok = 1;
        for (int i = 0; i < n; i++) {
            long long v = p[i];
            if (v < 0 || v >= (long long)N) { ok = 0; break; }
        }
        g_is64 = ok;
    }
}

// count: 2 edges per thread, vectorized loads of the dst half
__global__ void count_kernel(const void* ei, int E, int N) {
    int t = blockIdx.x * blockDim.x + threadIdx.x;
    int e = t * 2;
    if (e >= E) return;
    int d0, d1;
    if (g_is64) {
        longlong2 v = *(const longlong2*)((const long long*)ei + (size_t)E + e);
        d0 = (int)v.x; d1 = (int)v.y;
    } else {
        int2 v = *(const int2*)((const int*)ei + (size_t)E + e);
        d0 = v.x; d1 = v.y;
    }
    atomicAdd(&g_cnt[d0], 1);
    if (e + 1 < E) atomicAdd(&g_cnt[d1], 1);
}

// ---------------------------------------------------------------------------
// multi-block exclusive scan (scan1 also re-zeroes g_cnt for the next replay)
// ---------------------------------------------------------------------------
__global__ __launch_bounds__(1024) void scan1_kernel(int N) {
    __shared__ int ws[32];
    int tid = threadIdx.x, lane = tid & 31, w = tid >> 5;
    int i = blockIdx.x * 1024 + tid;
    int v = (i < N) ? g_cnt[i] : 0;
    if (i < N) g_cnt[i] = 0;           // reset for next graph replay
    int x = v;
    #pragma unroll
    for (int d = 1; d < 32; d <<= 1) {
        int t = __shfl_up_sync(0xffffffffu, x, d);
        if (lane >= d) x += t;
    }
    if (lane == 31) ws[w] = x;
    __syncthreads();
    if (tid < 32) {
        int s = ws[tid];
        #pragma unroll
        for (int d = 1; d < 32; d <<= 1) {
            int t = __shfl_up_sync(0xffffffffu, s, d);
            if (tid >= d) s += t;
        }
        ws[tid] = s;
    }
    __syncthreads();
    int incl = x + (w > 0 ? ws[w - 1] : 0);
    if (i < N) g_rowptr[i] = incl - v;
    if (tid == 1023) g_bsum[blockIdx.x] = incl;
}

__global__ void scan2_kernel(int NB, int N) {
    __shared__ int ws[4];
    int tid = threadIdx.x, lane = tid & 31, w = tid >> 5;
    int v = (tid < NB) ? g_bsum[tid] : 0;
    int x = v;
    #pragma unroll
    for (int d = 1; d < 32; d <<= 1) {
        int t = __shfl_up_sync(0xffffffffu, x, d);
        if (lane >= d) x += t;
    }
    if (lane == 31) ws[w] = x;
    __syncthreads();
    if (tid < 4) {
        int s = ws[tid];
        for (int d = 1; d < 4; d <<= 1) {
            int t = __shfl_up_sync(0xfu, s, d);
            if (tid >= d) s += t;
        }
        ws[tid] = s;
    }
    __syncthreads();
    int incl = x + (w > 0 ? ws[w - 1] : 0);
    if (tid < NB) g_boff[tid] = incl - v;
    if (tid == NB - 1) g_rowptr[N] = incl;
}

__global__ __launch_bounds__(1024) void scan3_kernel(int N) {
    int i = blockIdx.x * 1024 + threadIdx.x;
    if (i < N) {
        int r = g_rowptr[i] + g_boff[blockIdx.x];
        g_rowptr[i] = r;
        g_head[i] = r;
    }
}

// scatter: 2 edges per thread, vectorized loads
__global__ void scatter_kernel(const void* ei, int E) {
    int t = blockIdx.x * blockDim.x + threadIdx.x;
    int e = t * 2;
    if (e >= E) return;
    int s0, s1, d0, d1;
    if (g_is64) {
        longlong2 sv = *(const longlong2*)((const long long*)ei + e);
        longlong2 dv = *(const longlong2*)((const long long*)ei + (size_t)E + e);
        s0 = (int)sv.x; s1 = (int)sv.y; d0 = (int)dv.x; d1 = (int)dv.y;
    } else {
        int2 sv = *(const int2*)((const int*)ei + e);
        int2 dv = *(const int2*)((const int*)ei + (size_t)E + e);
        s0 = sv.x; s1 = sv.y; d0 = dv.x; d1 = dv.y;
    }
    int p0 = atomicAdd(&g_head[d0], 1);
    g_col[p0] = s0;
    if (e + 1 < E) {
        int p1 = atomicAdd(&g_head[d1], 1);
        g_col[p1] = s1;
    }
}

// ---------------------------------------------------------------------------
// W1 -> fragment-major fp16 (hi used by GEMM; lo slot kept but unused)
// ---------------------------------------------------------------------------
__global__ void convW_kernel(const float* __restrict__ W) {
    int t = blockIdx.x * 256 + threadIdx.x;
    if (t >= NCHUNK * 2 * 8 * 32) return;
    int lane = t & 31;
    int nt = (t >> 5) & 7;
    int r  = (t >> 8) & 1;
    int c  = t >> 9;
    int grp = lane >> 2, q = lane & 3;
    int k = c * 16 + r * 8 + q * 2;
    int n = nt * 8 + grp;
    float w0 = W[(size_t)k * HID + n];
    float w1 = W[(size_t)(k + 1) * HID + n];
    __half2 hh = __floats2half2_rn(w0, w1);
    g_wf[c * 1024 + (r * 8 + nt) * 32 + lane] = *(uint32_t*)&hh;
}

// ---------------------------------------------------------------------------
// GEMM1: h1[N,64] = x[N,512] @ W1 via mma.sync fp16, K=32 per iteration
// (2 chunks fused -> 16 iterations, halved barriers, MLP-4 prefetch).
// 256 threads = 8 warps x 16 rows. Fused attn1 epilogue (head == n-tile).
// APAD2=20: row offsets {0,4,8,12} mod 4 = 0 -> STS.128 aligned;
// (20*grp+q) mod 32 enumerates all banks -> conflict-free fragment LDS.
// ---------------------------------------------------------------------------
#define APAD2 20
__global__ __launch_bounds__(256) void gemm1_mma_kernel(const float* __restrict__ x,
                                                        const float* __restrict__ att_s,
                                                        const float* __restrict__ att_d,
                                                        int Nn) {
    __shared__ uint32_t sA[128 * APAD2];   // per row: words 0-7 = k0..15, 8-15 = k16..31
    __shared__ uint32_t sW[1024];          // 0..511 chunk even, 512..1023 chunk odd

    int tid = threadIdx.x;
    int w = tid >> 5, lane = tid & 31;
    int grp = lane >> 2, q = lane & 3;
    int row0 = blockIdx.x * 128;

    int arow = tid >> 1;
    int acol8 = (tid & 1) * 8;
    int grow_a = row0 + arow;
    const float* abase = x + (size_t)(grow_a < Nn ? grow_a : (Nn - 1)) * FIN + acol8;

    float acc[8][4];
    #pragma unroll
    for (int nt = 0; nt < 8; nt++)
        #pragma unroll
        for (int i = 0; i < 4; i++) acc[nt][i] = 0.f;

    // prologue prefetch: iteration 0 covers k 0..31
    float4 pa0 = *(const float4*)(abase + 0);
    float4 pa1 = *(const float4*)(abase + 4);
    float4 pa2 = *(const float4*)(abase + 16);
    float4 pa3 = *(const float4*)(abase + 20);
    uint2  pw0 = *(const uint2*)&g_wf[0 * 1024 + tid * 2];
    uint2  pw1 = *(const uint2*)&g_wf[1 * 1024 + tid * 2];

    #pragma unroll 1
    for (int t = 0; t < NCHUNK / 2; t++) {
        __syncthreads();
        {
            __half2 q0 = __floats2half2_rn(pa0.x, pa0.y);
            __half2 q1 = __floats2half2_rn(pa0.z, pa0.w);
            __half2 q2 = __floats2half2_rn(pa1.x, pa1.y);
            __half2 q3 = __floats2half2_rn(pa1.z, pa1.w);
            __half2 q4 = __floats2half2_rn(pa2.x, pa2.y);
            __half2 q5 = __floats2half2_rn(pa2.z, pa2.w);
            __half2 q6 = __floats2half2_rn(pa3.x, pa3.y);
            __half2 q7 = __floats2half2_rn(pa3.z, pa3.w);
            int off = arow * APAD2 + (tid & 1) * 4;
            *(uint4*)&sA[off]     = make_uint4(*(uint32_t*)&q0, *(uint32_t*)&q1,
                                               *(uint32_t*)&q2, *(uint32_t*)&q3);
            *(uint4*)&sA[off + 8] = make_uint4(*(uint32_t*)&q4, *(uint32_t*)&q5,
                                               *(uint32_t*)&q6, *(uint32_t*)&q7);
            *(uint2*)&sW[tid * 2]       = pw0;
            *(uint2*)&sW[512 + tid * 2] = pw1;
        }
        if (t + 1 < NCHUNK / 2) {
            const float* nb = abase + (t + 1) * 32;
            pa0 = *(const float4*)(nb + 0);
            pa1 = *(const float4*)(nb + 4);
            pa2 = *(const float4*)(nb + 16);
            pa3 = *(const float4*)(nb + 20);
            pw0 = *(const uint2*)&g_wf[(2 * t + 2) * 1024 + tid * 2];
            pw1 = *(const uint2*)&g_wf[(2 * t + 3) * 1024 + tid * 2];
        }
        __syncthreads();
        int ab = w * 16;
        #pragma unroll
        for (int sub = 0; sub < 2; sub++) {
            uint32_t a0 = sA[(ab + grp) * APAD2 + sub * 8 + q];
            uint32_t a1 = sA[(ab + 8 + grp) * APAD2 + sub * 8 + q];
            uint32_t a2 = sA[(ab + grp) * APAD2 + sub * 8 + 4 + q];
            uint32_t a3 = sA[(ab + 8 + grp) * APAD2 + sub * 8 + 4 + q];
            #pragma unroll
            for (int nt = 0; nt < 8; nt++) {
                uint32_t b0 = sW[sub * 512 + (0 * 8 + nt) * 32 + lane];
                uint32_t b1 = sW[sub * 512 + (1 * 8 + nt) * 32 + lane];
                mma_f16(acc[nt], a0, a1, a2, a3, b0, b1);
            }
        }
    }

    // epilogue: store h1 (packed fp16x2) + fused per-head attention dots
    int r0 = row0 + w * 16 + grp;
    int r1 = r0 + 8;
    #pragma unroll
    for (int nt = 0; nt < 8; nt++) {
        int col = nt * 8 + q * 2;
        int wordi = nt * 4 + q;            // col/2
        if (r0 < Nn) {
            __half2 hp = __floats2half2_rn(acc[nt][0], acc[nt][1]);
            g_h1h[(size_t)r0 * 32 + wordi] = *(uint32_t*)&hp;
        }
        if (r1 < Nn) {
            __half2 hp = __floats2half2_rn(acc[nt][2], acc[nt][3]);
            g_h1h[(size_t)r1 * 32 + wordi] = *(uint32_t*)&hp;
        }
        float2 a_s = *(const float2*)&att_s[col];
        float2 a_d = *(const float2*)&att_d[col];
        float p0s = acc[nt][0] * a_s.x + acc[nt][1] * a_s.y;
        float p0d = acc[nt][0] * a_d.x + acc[nt][1] * a_d.y;
        float p1s = acc[nt][2] * a_s.x + acc[nt][3] * a_s.y;
        float p1d = acc[nt][2] * a_d.x + acc[nt][3] * a_d.y;
        p0s += __shfl_xor_sync(0xffffffffu, p0s, 1);
        p0s += __shfl_xor_sync(0xffffffffu, p0s, 2);
        p0d += __shfl_xor_sync(0xffffffffu, p0d, 1);
        p0d += __shfl_xor_sync(0xffffffffu, p0d, 2);
        p1s += __shfl_xor_sync(0xffffffffu, p1s, 1);
        p1s += __shfl_xor_sync(0xffffffffu, p1s, 2);
        p1d += __shfl_xor_sync(0xffffffffu, p1d, 1);
        p1d += __shfl_xor_sync(0xffffffffu, p1d, 2);
        if (q == 0) {
            if (r0 < Nn) { g_as1[(size_t)r0 * NH1 + nt] = p0s; g_ad1[(size_t)r0 * NH1 + nt] = p0d; }
            if (r1 < Nn) { g_as1[(size_t)r1 * NH1 + nt] = p1s; g_ad1[(size_t)r1 * NH1 + nt] = p1d; }
        }
    }
}

// ---------------------------------------------------------------------------
// layer-1 fused softmax+aggregate, single pass. One warp per node.
// h1 packed fp16x2: one 32-bit word per lane -> one 128B line per edge gather.
// ---------------------------------------------------------------------------
__global__ __launch_bounds__(256) void agg1_kernel(const float* __restrict__ bias1, int N) {
    int node = (blockIdx.x * blockDim.x + threadIdx.x) >> 5;
    int lane = threadIdx.x & 31;
    if (node >= N) return;
    int start = g_rowptr[node];
    int deg   = g_rowptr[node + 1] - start;
    int hl = lane & 7;
    int hh = lane >> 2;

    float adv   = g_ad1[(size_t)node * NH1 + hl];
    float selfe = __expf(lrelu(g_as1[(size_t)node * NH1 + hl] + adv));
    uint32_t hw = g_h1h[(size_t)node * 32 + lane];
    float2 hv = __half22float2(*(__half2*)&hw);

    float ax = 0.f, ay = 0.f;
    float s = 0.f;
    for (int base = 0; base < deg; base += 4) {
        int idx = base + (lane >> 3);
        int j = 0; float wt = 0.f;
        if (idx < deg) {
            j = g_col[start + idx];
            wt = __expf(lrelu(g_as1[(size_t)j * NH1 + hl] + adv));
        }
        s += wt;
        int nb = min(4, deg - base);
        #pragma unroll
        for (int e = 0; e < 4; e++) {
            if (e >= nb) break;
            float we = __shfl_sync(0xffffffffu, wt, e * 8 + hh);
            int je   = __shfl_sync(0xffffffffu, j, e * 8);
            uint32_t vw = g_h1h[(size_t)je * 32 + lane];
            float2 v = __half22float2(*(__half2*)&vw);
            ax = fmaf(we, v.x, ax);
            ay = fmaf(we, v.y, ay);
        }
    }
    s += __shfl_xor_sync(0xffffffffu, s, 8);
    s += __shfl_xor_sync(0xffffffffu, s, 16);
    s += selfe;
    float inv = 1.f / (s + EPSV);
    float invB   = __shfl_sync(0xffffffffu, inv, hh);
    float selfeB = __shfl_sync(0xffffffffu, selfe, hh);
    ax = (ax + selfeB * hv.x) * invB;
    ay = (ay + selfeB * hv.y) * invB;
    float2 bb = *(const float2*)&bias1[2 * lane];
    ax += bb.x; ay += bb.y;
    ax = ax > 0.f ? ax : (__expf(ax) - 1.f);
    ay = ay > 0.f ? ay : (__expf(ay) - 1.f);
    *(float2*)&g_helu[(size_t)node * HID + 2 * lane] = make_float2(ax, ay);
}

// ---------------------------------------------------------------------------
// layer-2 GEMM (thread per node) + attention scalars
// ---------------------------------------------------------------------------
__global__ __launch_bounds__(256) void gemm2_kernel(const float* __restrict__ W2,
                                                    const float* __restrict__ att_s,
                                                    const float* __restrict__ att_d,
                                                    int N) {
    __shared__ float sW[HID * C2];
    __shared__ float sas[C2], sad[C2];
    int tid = threadIdx.x;
    for (int i = tid; i < HID * C2; i += blockDim.x) sW[i] = W2[i];
    if (tid < C2) { sas[tid] = att_s[tid]; sad[tid] = att_d[tid]; }
    __syncthreads();
    int n = blockIdx.x * blockDim.x + tid;
    if (n >= N) return;
    float acc[C2];
    #pragma unroll
    for (int c = 0; c < C2; c++) acc[c] = 0.f;
    const float* hr = &g_helu[(size_t)n * HID];
    #pragma unroll
    for (int k = 0; k < HID; k += 4) {
        float4 h4 = *(const float4*)&hr[k];
        #pragma unroll
        for (int c = 0; c < C2; c++) {
            acc[c] = fmaf(h4.x, sW[(k + 0) * C2 + c], acc[c]);
            acc[c] = fmaf(h4.y, sW[(k + 1) * C2 + c], acc[c]);
            acc[c] = fmaf(h4.z, sW[(k + 2) * C2 + c], acc[c]);
            acc[c] = fmaf(h4.w, sW[(k + 3) * C2 + c], acc[c]);
        }
    }
    #pragma unroll
    for (int c = 0; c < C2; c += 4)
        *(float4*)&g_y2[(size_t)n * C2 + c] = make_float4(acc[c], acc[c+1], acc[c+2], acc[c+3]);
    float ps = 0.f, pd = 0.f;
    #pragma unroll
    for (int c = 0; c < C2; c++) { ps = fmaf(acc[c], sas[c], ps); pd = fmaf(acc[c], sad[c], pd); }
    g_as2[n] = ps;
    g_ad2[n] = pd;
}

// ---------------------------------------------------------------------------
// layer-2 fused softmax+aggregate, single pass + bias + final softmax
// ---------------------------------------------------------------------------
__global__ __launch_bounds__(256) void agg2_kernel(const float* __restrict__ bias2,
                                                   float* __restrict__ out, int N) {
    int node = (blockIdx.x * blockDim.x + threadIdx.x) >> 5;
    int lane = threadIdx.x & 31;
    if (node >= N) return;
    int start = g_rowptr[node];
    int deg   = g_rowptr[node + 1] - start;

    float ad    = g_ad2[node];
    float selfe = __expf(lrelu(g_as2[node] + ad));
    int c = lane & 15, half = lane >> 4;

    float acc = 0.f;
    float s = 0.f;
    for (int base = 0; base < deg; base += 32) {
        int idx = base + lane;
        int j = 0; float wt = 0.f;
        if (idx < deg) {
            j = g_col[start + idx];
            wt = __expf(lrelu(g_as2[j] + ad));
        }
        s += wt;
        int nb = min(32, deg - base);
        for (int p = 0; p < nb; p += 2) {
            int e = p + half;
            float we = __shfl_sync(0xffffffffu, wt, e & 31);
            int je   = __shfl_sync(0xffffffffu, j, e & 31);
            if (e < nb) acc = fmaf(we, g_y2[(size_t)je * C2 + c], acc);
        }
    }
    #pragma unroll
    for (int d = 16; d >= 1; d >>= 1)
        s += __shfl_xor_sync(0xffffffffu, s, d);
    s += selfe;
    float inv = 1.f / (s + EPSV);

    acc += __shfl_xor_sync(0xffffffffu, acc, 16);
    acc = (acc + selfe * g_y2[(size_t)node * C2 + c]) * inv;
    acc += bias2[c];

    float mx = acc;
    #pragma unroll
    for (int d = 8; d >= 1; d >>= 1)
        mx = fmaxf(mx, __shfl_xor_sync(0xffffffffu, mx, d));
    float p = __expf(acc - mx);
    float ss = p;
    #pragma unroll
    for (int d = 8; d >= 1; d >>= 1)
        ss += __shfl_xor_sync(0xffffffffu, ss, d);
    float soft = p / ss;

    if (lane < 16) {
        out[(size_t)node * C2 + c] = soft;
        out[(size_t)N * C2 + (size_t)node * C2 + c] = acc;
    }
}

// ---------------------------------------------------------------------------
// launch: CSR build (default stream) concurrent with convW+gemm1 (s2),
// with serial fallback if stream/event creation fails.
// ---------------------------------------------------------------------------
extern "C" void kernel_launch(void* const* d_in, const int* in_sizes, int n_in,
                              void* d_out, int out_size) {
    const float* x   = (const float*)d_in[0];
    const void*  ei  = d_in[1];
    const float* W1  = (const float*)d_in[2];
    const float* as1 = (const float*)d_in[3];
    const float* ad1 = (const float*)d_in[4];
    const float* b1  = (const float*)d_in[5];
    const float* W2  = (const float*)d_in[6];
    const float* as2 = (const float*)d_in[7];
    const float* ad2 = (const float*)d_in[8];
    const float* b2  = (const float*)d_in[9];
    float* out = (float*)d_out;

    int E = in_sizes[1] / 2;
    int N = in_sizes[0] / FIN;
    int NB = (N + 1023) / 1024;
    int EB2 = ((E + 1) / 2 + 255) / 256;

    static cudaStream_t s2 = nullptr;
    static cudaEvent_t evFork = nullptr, evJoin = nullptr;
    static int streams_ok = -1;
    if (streams_ok < 0) {
        streams_ok = 1;
        if (cudaStreamCreateWithFlags(&s2, cudaStreamNonBlocking) != cudaSuccess) streams_ok = 0;
        if (streams_ok &&
            cudaEventCreateWithFlags(&evFork, cudaEventDisableTiming) != cudaSuccess) streams_ok = 0;
        if (streams_ok &&
            cudaEventCreateWithFlags(&evJoin, cudaEventDisableTiming) != cudaSuccess) streams_ok = 0;
    }

    if (streams_ok) {
        // fork: side stream runs the GEMM1 chain (independent of edge data)
        cudaEventRecord(evFork, 0);
        cudaStreamWaitEvent(s2, evFork, 0);
        convW_kernel<<<64, 256, 0, s2>>>(W1);
        gemm1_mma_kernel<<<(N + 127) / 128, 256, 0, s2>>>(x, as1, ad1, N);
        cudaEventRecord(evJoin, s2);

        // default stream: CSR build chain
        detect_kernel<<<1, 32>>>((const long long*)ei, N, E);
        count_kernel<<<EB2, 256>>>(ei, E, N);
        scan1_kernel<<<NB, 1024>>>(N);
        scan2_kernel<<<1, 128>>>(NB, N);
        scan3_kernel<<<NB, 1024>>>(N);
        scatter_kernel<<<EB2, 256>>>(ei, E);

        cudaStreamWaitEvent(0, evJoin, 0);
    } else {
        // serial fallback
        detect_kernel<<<1, 32>>>((const long long*)ei, N, E);
        count_kernel<<<EB2, 256>>>(ei, E, N);
        scan1_kernel<<<NB, 1024>>>(N);
        scan2_kernel<<<1, 128>>>(NB, N);
        scan3_kernel<<<NB, 1024>>>(N);
        scatter_kernel<<<EB2, 256>>>(ei, E);
        convW_kernel<<<64, 256>>>(W1);
        gemm1_mma_kernel<<<(N + 127) / 128, 256>>>(x, as1, ad1, N);
    }

    agg1_kernel<<<(N + 7) / 8, 256>>>(b1, N);
    gemm2_kernel<<<(N + 255) / 256, 256>>>(W2, as2, ad2, N);
    agg2_kernel<<<(N + 7) / 8, 256>>>(b2, out, N);
}